// round 11
// baseline (speedup 1.0000x reference)
#include <cuda_runtime.h>
#include <math.h>

#define Bsz 128
#define Tlen 48
#define Dm 512
#define NBLK 128
#define NTHR 512

// ---------------- global scratch ---------------------------------------------
__device__ float g_w[Bsz*Tlen*64];
__device__ unsigned long long g_code[Bsz*Tlen*2];
__device__ int g_src[Bsz*Tlen];
__device__ float g_read[Bsz*Dm];
__device__ float g_f[Bsz*Dm];
__device__ float g_we[Bsz*Dm];
__device__ float g_ft[Tlen*Bsz*Dm];
__device__ float g_H[(Tlen+1)*Bsz*Dm];
__device__ float g_C[(Tlen+1)*Bsz*Dm];
// barriers: monotonic counters (graph-replay safe). group g uses slot g*32 (128B pad)
__device__ unsigned g_count = 0;
__device__ volatile unsigned g_sense = 0;
__device__ unsigned g_gcnt[8*32];
__device__ volatile unsigned g_gsense[8*32];

__device__ __forceinline__ float sigm(float x) { return 1.0f / (1.0f + expf(-x)); }

// per-warp-group (128-thread) named barrier: ids 1..4 (0 is __syncthreads)
__device__ __forceinline__ void barg(int g) {
    asm volatile("bar.sync %0, 128;" :: "r"(g + 1) : "memory");
}

// smem layout (floats): [0,32768) memS | [32768,+2560) As | [35328,+4608) Ws
// [39936,+9216) part | [49152,+1024) wT | [50176,+1024) wN | [51200,+16) ints
#define OFF_AS   32768
#define OFF_WS   35328
#define OFF_PART 39936
#define OFF_WT   49152
#define OFF_WN   50176
#define OFF_I16  51200
#define SMEM_FLOATS 51232
#define SMEM_BYTES (SMEM_FLOATS * 4)

// ---------------- global grid barrier (monotonic, boundary uses) --------------
__device__ __forceinline__ void gsync(unsigned& ls) {
    __syncthreads();
    if (threadIdx.x == 0) {
        unsigned target = ls + 1u;
        __threadfence();                              // release
        unsigned a = atomicAdd(&g_count, 1u) + 1u;
        if (a == target * (unsigned)NBLK) g_sense = target;
        while (g_sense != target) { }
        ls = target;
        __threadfence();                              // acquire (L1 flush)
    }
    __syncthreads();
}

// ---------------- group barrier: 16 blocks sharing one row-group --------------
__device__ __forceinline__ void gsync_grp(unsigned& ls, int grp32) {
    __syncthreads();
    if (threadIdx.x == 0) {
        unsigned target = ls + 1u;
        __threadfence();                              // release
        unsigned a = atomicAdd(&g_gcnt[grp32], 1u) + 1u;
        if (a == target * 16u) g_gsense[grp32] = target;
        while (g_gsense[grp32] != target) { }
        ls = target;
        __threadfence();                              // acquire (L1 flush)
    }
    __syncthreads();
}

__device__ __forceinline__ void fma16(float (&acc)[4][4], float4 a, float4 w) {
    acc[0][0]=fmaf(a.x,w.x,acc[0][0]); acc[0][1]=fmaf(a.x,w.y,acc[0][1]);
    acc[0][2]=fmaf(a.x,w.z,acc[0][2]); acc[0][3]=fmaf(a.x,w.w,acc[0][3]);
    acc[1][0]=fmaf(a.y,w.x,acc[1][0]); acc[1][1]=fmaf(a.y,w.y,acc[1][1]);
    acc[1][2]=fmaf(a.y,w.z,acc[1][2]); acc[1][3]=fmaf(a.y,w.w,acc[1][3]);
    acc[2][0]=fmaf(a.z,w.x,acc[2][0]); acc[2][1]=fmaf(a.z,w.y,acc[2][1]);
    acc[2][2]=fmaf(a.z,w.z,acc[2][2]); acc[2][3]=fmaf(a.z,w.w,acc[2][3]);
    acc[3][0]=fmaf(a.w,w.x,acc[3][0]); acc[3][1]=fmaf(a.w,w.y,acc[3][1]);
    acc[3][2]=fmaf(a.w,w.z,acc[3][2]); acc[3][3]=fmaf(a.w,w.w,acc[3][3]);
}

// ---------------- addressing GEMM: g_w[6144,64] = ktab[q] @ Mk^T -------------
__device__ void stage_addr(float* sm, const float* __restrict__ Mk,
                           const float* __restrict__ ktab, const int* __restrict__ q)
{
    float* As = sm + OFF_AS;      // [32][68]
    float* Ws = sm + OFF_WS;      // [32][36]
    float* part = sm + OFF_PART;  // [4][64][36]
    const int tid = threadIdx.x;
    const int s = tid >> 7, pos = tid & 127, rg = pos >> 3, cg = pos & 7;
    for (int tile = blockIdx.x; tile < 192; tile += NBLK) {
        const int row0 = (tile >> 1) * 64, cc0 = (tile & 1) * 32;
        float acc[4][4] = {};
#pragma unroll 1
        for (int ch = 0; ch < 16; ch++) {
            const int kb = ch * 32;
            {
                int rr = tid >> 3, kq = tid & 7;
                int qi = q[row0 + rr];
                float4 v = *(const float4*)(ktab + (size_t)qi * Dm + kb + kq * 4);
                float* a = As + (kq * 4) * 68 + rr;
                a[0] = v.x; a[68] = v.y; a[136] = v.z; a[204] = v.w;
            }
            if (tid < 256) {
                int n = tid >> 3, kq = tid & 7;
                float4 v = *(const float4*)(Mk + (size_t)(cc0 + n) * Dm + kb + kq * 4);
                float* w = Ws + (kq * 4) * 36 + n;
                w[0] = v.x; w[36] = v.y; w[72] = v.z; w[108] = v.w;
            }
            __syncthreads();
#pragma unroll
            for (int kk = 0; kk < 8; kk++) {
                int k = s * 8 + kk;
                float4 a4 = *(const float4*)(As + k * 68 + rg * 4);
                float4 w4 = *(const float4*)(Ws + k * 36 + cg * 4);
                fma16(acc, a4, w4);
            }
            __syncthreads();
        }
#pragma unroll
        for (int j = 0; j < 4; j++)
            *(float4*)(part + s * 2304 + (rg * 4 + j) * 36 + cg * 4) =
                make_float4(acc[j][0], acc[j][1], acc[j][2], acc[j][3]);
        __syncthreads();
        {
            int rr = tid >> 3, cgx = tid & 7;
            float4 v = make_float4(0.f, 0.f, 0.f, 0.f);
#pragma unroll
            for (int p = 0; p < 4; p++) {
                float4 u = *(const float4*)(part + p * 2304 + rr * 36 + cgx * 4);
                v.x += u.x; v.y += u.y; v.z += u.z; v.w += u.w;
            }
            *(float4*)(g_w + (size_t)(row0 + rr) * 64 + cc0 + cgx * 4) = v;
        }
        __syncthreads();
    }
}

// ---------------- softmax + triangular membership codes ----------------------
__device__ void stage_softmax(float* sm)
{
    unsigned char* ivb = (unsigned char*)(sm + OFF_WT);  // [16][64]
    const int wp = threadIdx.x >> 5, lane = threadIdx.x & 31;
    for (int rr = wp; rr < 48; rr += 16) {
        const int row = blockIdx.x * 48 + rr;
        float v0 = g_w[row * 64 + lane];
        float v1 = g_w[row * 64 + 32 + lane];
        float mx = fmaxf(v0, v1);
        for (int o = 16; o; o >>= 1) mx = fmaxf(mx, __shfl_xor_sync(0xffffffffu, mx, o));
        float e0 = expf(v0 - mx), e1 = expf(v1 - mx);
        float ss = e0 + e1;
        for (int o = 16; o; o >>= 1) ss += __shfl_xor_sync(0xffffffffu, ss, o);
        float inv = 1.0f / ss;
        float w0 = e0 * inv, w1 = e1 * inv;
        g_w[row * 64 + lane] = w0;
        g_w[row * 64 + 32 + lane] = w1;
        auto ivf = [](float w) -> int {
            float m = fmaxf(fminf((w - 0.075f) / (0.088f - 0.075f),
                                  (1.0f - w) / (1.0f - 0.088f)), 0.0f);
            return (m >= 0.6f) ? 2 : ((m >= 0.1f) ? 1 : 0);
        };
        ivb[wp * 64 + lane] = (unsigned char)ivf(w0);
        ivb[wp * 64 + 32 + lane] = (unsigned char)ivf(w1);
        __syncwarp();
        if (lane == 0) {
            unsigned long long c0 = 0ull, c1 = 0ull;
            for (int i = 0; i < 32; i++) {
                c0 |= (unsigned long long)ivb[wp * 64 + i] << (2 * i);
                c1 |= (unsigned long long)ivb[wp * 64 + 32 + i] << (2 * i);
            }
            g_code[row * 2] = c0;
            g_code[row * 2 + 1] = c1;
        }
        __syncwarp();
    }
}

// ---------------- src scan + memS / H0 / C0 / read_0 init --------------------
__device__ void stage_init(float* sm, const float* __restrict__ Mv0,
                           const float* __restrict__ hx0, const float* __restrict__ cx0,
                           int r0, int c0)
{
    float* memS = sm;
    float* wT = sm + OFF_WT;
    const int tid = threadIdx.x;
    if (tid < Tlen) {
        const int b = blockIdx.x, i = tid;
        unsigned long long cc0 = g_code[(b * Tlen + i) * 2];
        unsigned long long cc1 = g_code[(b * Tlen + i) * 2 + 1];
        int sv = i - 1;
        for (int j = i - 1; j >= 0; j--)
            if (g_code[(b * Tlen + j) * 2] == cc0 && g_code[(b * Tlen + j) * 2 + 1] == cc1) { sv = j; break; }
        g_src[b * Tlen + i] = sv;
    }
    for (int i = tid; i < 32768; i += NTHR) {
        int m = (i >> 5) & 63, cc = i & 31;
        memS[i] = Mv0[m * Dm + c0 + cc];
    }
    for (int i = tid; i < 1024; i += NTHR) {
        int bl = i >> 6, m = i & 63;
        wT[i] = g_w[((r0 + bl) * Tlen) * 64 + m];
    }
    __syncthreads();
    const int rr = tid >> 5, cc = tid & 31;
    const int b = r0 + rr, col = c0 + cc;
    g_H[(size_t)b * Dm + col] = hx0[col];
    g_C[(size_t)b * Dm + col] = cx0[col];
    float racc = 0.f;
#pragma unroll 4
    for (int m = 0; m < 64; m++)
        racc = fmaf(wT[rr * 64 + m], memS[(rr * 64 + m) * 32 + cc], racc);
    g_read[(size_t)b * Dm + col] = racc;
}

// ---------------- f / we GEMM (K=1024, per-group chunks, NAMED barriers) -----
template<int MODE>   // 0: f = tanh(.), X=g_read, tab=ktab ; 1: we = raw, X=g_f, tab=xtab
__device__ void stage_fwe(float* sm, const float* __restrict__ W, const float* __restrict__ bias,
                          const float* __restrict__ tab, const int* __restrict__ q,
                          const int* __restrict__ r, int t, int r0, int c0)
{
    float* As = sm + OFF_AS;      // per group g: [32][20] at g*640
    float* Ws = sm + OFF_WS;      // per group g: [32][36] at g*1152
    float* part = sm + OFF_PART;  // [16][16][36]
    int* sQ = (int*)(sm + OFF_I16);
    const int tid = threadIdx.x;
    const int g = tid >> 7, gt = tid & 127;
    const int s = gt >> 5, pos = gt & 31, rg = pos >> 3, cg = pos & 7;
    if (tid < 16) {
        int b = r0 + tid;
        int qi = q[b * Tlen + t];
        sQ[tid] = (MODE == 0) ? qi : (qi + 2000 * r[b * Tlen + t]);
    }
    __syncthreads();
    const float* X = (MODE == 0) ? g_read : g_f;
    float acc[4][4] = {};
#pragma unroll 1
    for (int ch = 0; ch < 8; ch++) {
        const int kb = g * 256 + ch * 32;
        {
            int rr = gt >> 3, kq = gt & 7;
            const float* srcp = (g < 2)
                ? X + (size_t)(r0 + rr) * Dm + kb + kq * 4
                : tab + (size_t)sQ[rr] * Dm + (kb - Dm) + kq * 4;
            float4 v = *(const float4*)srcp;
            float* a = As + g * 640 + (kq * 4) * 20 + rr;
            a[0] = v.x; a[20] = v.y; a[40] = v.z; a[60] = v.w;
        }
#pragma unroll
        for (int h = 0; h < 2; h++) {
            int i2 = gt * 2 + h;
            int n = i2 >> 3, kq = i2 & 7;
            float4 v = *(const float4*)(W + (size_t)(c0 + n) * 1024 + kb + kq * 4);
            float* w = Ws + g * 1152 + (kq * 4) * 36 + n;
            w[0] = v.x; w[36] = v.y; w[72] = v.z; w[108] = v.w;
        }
        barg(g);
#pragma unroll
        for (int kk = 0; kk < 8; kk++) {
            int k = s * 8 + kk;
            float4 a4 = *(const float4*)(As + g * 640 + k * 20 + rg * 4);
            float4 w4 = *(const float4*)(Ws + g * 1152 + k * 36 + cg * 4);
            fma16(acc, a4, w4);
        }
        barg(g);
    }
    const int sid = g * 4 + s;
#pragma unroll
    for (int j = 0; j < 4; j++)
        *(float4*)(part + sid * 576 + (rg * 4 + j) * 36 + cg * 4) =
            make_float4(acc[j][0], acc[j][1], acc[j][2], acc[j][3]);
    __syncthreads();
    {
        const int rr = tid >> 5, cc = tid & 31;
        float v = 0.f;
#pragma unroll
        for (int p = 0; p < 16; p++) v += part[p * 576 + rr * 36 + cc];
        v += bias[c0 + cc];
        const int b = r0 + rr;
        if (MODE == 0) {
            v = tanhf(v);
            g_f[(size_t)b * Dm + c0 + cc] = v;
            g_ft[((size_t)t * Bsz + b) * Dm + c0 + cc] = v;
        } else {
            g_we[(size_t)b * Dm + c0 + cc] = v;
        }
    }
}

// ---------------- e/a GEMMs + smem memory update (NAMED barriers) ------------
__device__ void stage_ea(float* sm, const float* __restrict__ We, const float* __restrict__ be,
                         const float* __restrict__ Wa, const float* __restrict__ ba,
                         int t, int r0, int c0)
{
    float* memS = sm;
    float* As = sm + OFF_AS;
    float* Ws = sm + OFF_WS;
    float* part = sm + OFF_PART;
    float* wT = sm + OFF_WT;
    float* wN = sm + OFF_WN;
    const int tid = threadIdx.x;
    const int g = tid >> 7, gt = tid & 127;
    const int s = gt >> 5, pos = gt & 31, rg = pos >> 3, cg = pos & 7;
    for (int i = tid; i < 1024; i += NTHR) {
        int bl = i >> 6, m = i & 63;
        wT[i] = g_w[((r0 + bl) * Tlen + t) * 64 + m];
        wN[i] = (t + 1 < Tlen) ? g_w[((r0 + bl) * Tlen + t + 1) * 64 + m] : 0.0f;
    }
    const float* W = (g < 2) ? We : Wa;
    float acc[4][4] = {};
#pragma unroll 1
    for (int ch = 0; ch < 8; ch++) {
        const int kb = (g & 1) * 256 + ch * 32;
        {
            int rr = gt >> 3, kq = gt & 7;
            float4 v = *(const float4*)(g_we + (size_t)(r0 + rr) * Dm + kb + kq * 4);
            float* a = As + g * 640 + (kq * 4) * 20 + rr;
            a[0] = v.x; a[20] = v.y; a[40] = v.z; a[60] = v.w;
        }
#pragma unroll
        for (int h = 0; h < 2; h++) {
            int i2 = gt * 2 + h;
            int n = i2 >> 3, kq = i2 & 7;
            float4 v = *(const float4*)(W + (size_t)(c0 + n) * Dm + kb + kq * 4);
            float* w = Ws + g * 1152 + (kq * 4) * 36 + n;
            w[0] = v.x; w[36] = v.y; w[72] = v.z; w[108] = v.w;
        }
        barg(g);
#pragma unroll
        for (int kk = 0; kk < 8; kk++) {
            int k = s * 8 + kk;
            float4 a4 = *(const float4*)(As + g * 640 + k * 20 + rg * 4);
            float4 w4 = *(const float4*)(Ws + g * 1152 + k * 36 + cg * 4);
            fma16(acc, a4, w4);
        }
        barg(g);
    }
    const int sid = g * 4 + s;
#pragma unroll
    for (int j = 0; j < 4; j++)
        *(float4*)(part + sid * 576 + (rg * 4 + j) * 36 + cg * 4) =
            make_float4(acc[j][0], acc[j][1], acc[j][2], acc[j][3]);
    __syncthreads();
    {
        const int rr = tid >> 5, cc = tid & 31;
        float ve = 0.f, va = 0.f;
#pragma unroll
        for (int p = 0; p < 8; p++)  ve += part[p * 576 + rr * 36 + cc];
#pragma unroll
        for (int p = 8; p < 16; p++) va += part[p * 576 + rr * 36 + cc];
        ve = sigm(ve + be[c0 + cc]);
        va = tanhf(va + ba[c0 + cc]);
        float racc = 0.f;
#pragma unroll 4
        for (int m = 0; m < 64; m++) {
            float wt = wT[rr * 64 + m], wn = wN[rr * 64 + m];
            float* p = &memS[(rr * 64 + m) * 32 + cc];
            float v = *p;
            v = v * (1.0f - wt * ve) + wt * va;
            *p = v;
            racc = fmaf(wn, v, racc);
        }
        g_read[(size_t)(r0 + rr) * Dm + c0 + cc] = racc;
    }
}

// ---------------- hop-LSTM step (per-group A staging, NAMED barriers) --------
__device__ void stage_lstm(float* sm, const float* __restrict__ Wih, const float* __restrict__ Whh,
                           const float* __restrict__ bih, const float* __restrict__ bhh,
                           int t, int r0, int c0)
{
    float* As = sm + OFF_AS;      // per group g: [32][20] at g*640
    float* Ws = sm + OFF_WS;
    float* part = sm + OFF_PART;
    int* s16 = (int*)(sm + OFF_I16);
    const int tid = threadIdx.x;
    const int g = tid >> 7, gt = tid & 127;
    const int s = gt >> 5, pos = gt & 31, rg = pos >> 3, cg = pos & 7;
    if (tid < 16) s16[tid] = g_src[(r0 + tid) * Tlen + t] + 1;
    __syncthreads();
    float acc[4][4] = {};
#pragma unroll 1
    for (int ch = 0; ch < 32; ch++) {
        const int kb = ch * 32;
        {   // each group stages its own copy of the A chunk (no cross-group dep)
            int rr = gt >> 3, kq = gt & 7;
            const float* srcp = (kb < Dm)
                ? g_ft + ((size_t)t * Bsz + r0 + rr) * Dm + kb + kq * 4
                : g_H + ((size_t)s16[rr] * Bsz + r0 + rr) * Dm + (kb - Dm) + kq * 4;
            float4 v = *(const float4*)srcp;
            float* a = As + g * 640 + (kq * 4) * 20 + rr;
            a[0] = v.x; a[20] = v.y; a[40] = v.z; a[60] = v.w;
        }
#pragma unroll
        for (int h = 0; h < 2; h++) {
            int i2 = gt * 2 + h;
            int n = i2 >> 3, kq = i2 & 7;
            const float* wsrc = (kb < Dm)
                ? Wih + (size_t)(g * Dm + c0 + n) * Dm + kb + kq * 4
                : Whh + (size_t)(g * Dm + c0 + n) * Dm + (kb - Dm) + kq * 4;
            float4 v = *(const float4*)wsrc;
            float* w = Ws + g * 1152 + (kq * 4) * 36 + n;
            w[0] = v.x; w[36] = v.y; w[72] = v.z; w[108] = v.w;
        }
        barg(g);
#pragma unroll
        for (int kk = 0; kk < 8; kk++) {
            int k = s * 8 + kk;
            float4 a4 = *(const float4*)(As + g * 640 + k * 20 + rg * 4);
            float4 w4 = *(const float4*)(Ws + g * 1152 + k * 36 + cg * 4);
            fma16(acc, a4, w4);
        }
        barg(g);
    }
    const int sid = g * 4 + s;
#pragma unroll
    for (int j = 0; j < 4; j++)
        *(float4*)(part + sid * 576 + (rg * 4 + j) * 36 + cg * 4) =
            make_float4(acc[j][0], acc[j][1], acc[j][2], acc[j][3]);
    __syncthreads();
    {
        const int rr = tid >> 5, cc = tid & 31;
        float gi = 0.f, gf = 0.f, gg = 0.f, go = 0.f;
#pragma unroll
        for (int p = 0; p < 4; p++)   gi += part[p * 576 + rr * 36 + cc];
#pragma unroll
        for (int p = 4; p < 8; p++)   gf += part[p * 576 + rr * 36 + cc];
#pragma unroll
        for (int p = 8; p < 12; p++)  gg += part[p * 576 + rr * 36 + cc];
#pragma unroll
        for (int p = 12; p < 16; p++) go += part[p * 576 + rr * 36 + cc];
        const int b = r0 + rr, col = c0 + cc;
        gi += bih[col] + bhh[col];
        gf += bih[512 + col] + bhh[512 + col];
        gg += bih[1024 + col] + bhh[1024 + col];
        go += bih[1536 + col] + bhh[1536 + col];
        float cin = g_C[((size_t)s16[rr] * Bsz + b) * Dm + col];
        float cn = sigm(gf) * cin + sigm(gi) * tanhf(gg);
        float hn = sigm(go) * tanhf(cn);
        g_C[((size_t)(t + 1) * Bsz + b) * Dm + col] = cn;
        g_H[((size_t)(t + 1) * Bsz + b) * Dm + col] = hn;
    }
}

// ---------------- prediction head --------------------------------------------
__device__ void stage_head(const float* __restrict__ Wp, const float* __restrict__ bp,
                           float* __restrict__ out)
{
    const int wp = threadIdx.x >> 5, lane = threadIdx.x & 31;
    for (int bt = blockIdx.x * 16 + wp; bt < Bsz * Tlen; bt += NBLK * 16) {
        const int b = bt / Tlen, t = bt % Tlen;
        const float* h = &g_H[((size_t)(t + 1) * Bsz + b) * Dm];
        float s = 0.f;
        for (int i = lane; i < Dm; i += 32) s = fmaf(h[i], Wp[i], s);
        for (int o = 16; o; o >>= 1) s += __shfl_xor_sync(0xffffffffu, s, o);
        if (lane == 0) out[bt] = sigm(s + bp[0]);
    }
}

// ---------------- the single persistent kernel -------------------------------
__global__ void __launch_bounds__(NTHR, 1) k_persist(
    const int* __restrict__ q, const int* __restrict__ r,
    const float* __restrict__ Mk, const float* __restrict__ Mv0,
    const float* __restrict__ ktab, const float* __restrict__ xtab,
    const float* __restrict__ We, const float* __restrict__ be,
    const float* __restrict__ Wadd, const float* __restrict__ badd,
    const float* __restrict__ Wa, const float* __restrict__ ba,
    const float* __restrict__ Wf, const float* __restrict__ bf,
    const float* __restrict__ Wih, const float* __restrict__ Whh,
    const float* __restrict__ bih, const float* __restrict__ bhh,
    const float* __restrict__ hx0, const float* __restrict__ cx0,
    const float* __restrict__ Wp, const float* __restrict__ bp,
    float* __restrict__ out)
{
    extern __shared__ float sm[];
    const int grp = blockIdx.x & 7;
    const int grp32 = grp * 32;
    unsigned ls = 0, lsr = 0;
    if (threadIdx.x == 0) { ls = g_sense; lsr = g_gsense[grp32]; }
    const int r0 = grp * 16;
    const int c0 = (blockIdx.x >> 3) * 32;

    stage_addr(sm, Mk, ktab, q);                          gsync(ls);
    stage_softmax(sm);                                    gsync(ls);
    stage_init(sm, Mv0, hx0, cx0, r0, c0);                gsync(ls);

    // sequential region: only the 16 blocks sharing r0 exchange data -> group syncs
    for (int t = 0; t < Tlen; t++) {
        stage_fwe<0>(sm, Wf, bf, ktab, q, r, t, r0, c0);  gsync_grp(lsr, grp32);
        stage_fwe<1>(sm, Wa, ba, xtab, q, r, t, r0, c0);  gsync_grp(lsr, grp32);
        stage_ea(sm, We, be, Wadd, badd, t, r0, c0);      gsync_grp(lsr, grp32);
    }
    for (int t = 0; t < Tlen; t++) {
        stage_lstm(sm, Wih, Whh, bih, bhh, t, r0, c0);    gsync_grp(lsr, grp32);
    }
    gsync(ls);                                            // head reads all rows
    stage_head(Wp, bp, out);
}

// ----------------------------------------------------------------------------
extern "C" void kernel_launch(void* const* d_in, const int* in_sizes, int n_in,
                              void* d_out, int out_size)
{
    const int*   q    = (const int*)d_in[0];
    const int*   r    = (const int*)d_in[1];
    const float* Mk   = (const float*)d_in[2];
    const float* Mv0  = (const float*)d_in[3];
    const float* ktab = (const float*)d_in[4];
    const float* xtab = (const float*)d_in[5];
    const float* We   = (const float*)d_in[6];
    const float* be   = (const float*)d_in[7];
    const float* Wadd = (const float*)d_in[8];
    const float* badd = (const float*)d_in[9];
    const float* Wa   = (const float*)d_in[10];
    const float* ba   = (const float*)d_in[11];
    const float* Wf   = (const float*)d_in[12];
    const float* bf   = (const float*)d_in[13];
    const float* Wih  = (const float*)d_in[14];
    const float* Whh  = (const float*)d_in[15];
    const float* bih  = (const float*)d_in[16];
    const float* bhh  = (const float*)d_in[17];
    const float* hx0  = (const float*)d_in[18];
    const float* cx0  = (const float*)d_in[19];
    const float* Wp   = (const float*)d_in[20];
    const float* bp   = (const float*)d_in[21];
    float* out = (float*)d_out;

    static bool attr_set = false;
    if (!attr_set) {
        cudaFuncSetAttribute(k_persist, cudaFuncAttributeMaxDynamicSharedMemorySize, SMEM_BYTES);
        attr_set = true;
    }
    k_persist<<<NBLK, NTHR, SMEM_BYTES>>>(q, r, Mk, Mv0, ktab, xtab, We, be, Wadd, badd,
                                          Wa, ba, Wf, bf, Wih, Whh, bih, bhh,
                                          hx0, cx0, Wp, bp, out);
}

// round 12
// speedup vs baseline: 1.3422x; 1.3422x over previous
#include <cuda_runtime.h>
#include <math.h>

#define Bsz 128
#define Tlen 48
#define Dm 512
#define NBLK 128
#define NTHR 512

// ---------------- global scratch ---------------------------------------------
__device__ float g_w[Bsz*Tlen*64];
__device__ unsigned long long g_code[Bsz*Tlen*2];
__device__ int g_src[Bsz*Tlen];
__device__ float g_read[Bsz*Dm];
__device__ float g_f[Bsz*Dm];
__device__ float g_we[Bsz*Dm];
__device__ float g_ft[Tlen*Bsz*Dm];
__device__ float g_H[(Tlen+1)*Bsz*Dm];
__device__ float g_C[(Tlen+1)*Bsz*Dm];
// barriers: monotonic counters (graph-replay safe). group g uses slot g*32 (128B pad)
__device__ unsigned g_count = 0;
__device__ volatile unsigned g_sense = 0;
__device__ unsigned g_gcnt[8*32];
__device__ volatile unsigned g_gsense[8*32];

__device__ __forceinline__ float sigm(float x) { return 1.0f / (1.0f + expf(-x)); }

// per-warp-group (128-thread) named barrier: ids 1..4 (0 is __syncthreads)
__device__ __forceinline__ void barg(int g) {
    asm volatile("bar.sync %0, 128;" :: "r"(g + 1) : "memory");
}

// smem layout (floats):
// [0,32768) memS | AS 4x640 | WS 4x1184 (W buf0, swizzled row-major) |
// PART 16x576 (also overlays W buf1 per group at g*2304) | wT | wN | i16
#define OFF_AS   32768
#define OFF_WS   35328
#define OFF_PART 40064
#define OFF_WT   49280
#define OFF_WN   50304
#define OFF_I16  51328
#define SMEM_FLOATS 51344
#define SMEM_BYTES (SMEM_FLOATS * 4)

// W smem swizzled row-major offset for column c (floats): bank = 20c mod 32 -> conflict-free
#define WOFF(c) ((c) * 36 + (((c) >> 2) << 2))

// ---------------- cp.async helpers --------------------------------------------
__device__ __forceinline__ void cpa16(unsigned dst, const float* src) {
    asm volatile("cp.async.cg.shared.global [%0], [%1], 16;" :: "r"(dst), "l"(src));
}
__device__ __forceinline__ void cpa_commit() {
    asm volatile("cp.async.commit_group;" ::: "memory");
}
__device__ __forceinline__ void cpa_wait1() {
    asm volatile("cp.async.wait_group 1;" ::: "memory");
}
__device__ __forceinline__ void cpa_wait0() {
    asm volatile("cp.async.wait_group 0;" ::: "memory");
}

// ---------------- global grid barrier (monotonic, boundary uses) --------------
__device__ __forceinline__ void gsync(unsigned& ls) {
    __syncthreads();
    if (threadIdx.x == 0) {
        unsigned target = ls + 1u;
        __threadfence();                              // release
        unsigned a = atomicAdd(&g_count, 1u) + 1u;
        if (a == target * (unsigned)NBLK) g_sense = target;
        while (g_sense != target) { }
        ls = target;
        __threadfence();                              // acquire
    }
    __syncthreads();
}

// ---------------- group barrier: 16 blocks sharing one row-group --------------
__device__ __forceinline__ void gsync_grp(unsigned& ls, int grp32) {
    __syncthreads();
    if (threadIdx.x == 0) {
        unsigned target = ls + 1u;
        __threadfence();                              // release
        unsigned a = atomicAdd(&g_gcnt[grp32], 1u) + 1u;
        if (a == target * 16u) g_gsense[grp32] = target;
        while (g_gsense[grp32] != target) { }
        ls = target;
        __threadfence();                              // acquire
    }
    __syncthreads();
}

__device__ __forceinline__ void fma16(float (&acc)[4][4], float4 a, float4 w) {
    acc[0][0]=fmaf(a.x,w.x,acc[0][0]); acc[0][1]=fmaf(a.x,w.y,acc[0][1]);
    acc[0][2]=fmaf(a.x,w.z,acc[0][2]); acc[0][3]=fmaf(a.x,w.w,acc[0][3]);
    acc[1][0]=fmaf(a.y,w.x,acc[1][0]); acc[1][1]=fmaf(a.y,w.y,acc[1][1]);
    acc[1][2]=fmaf(a.y,w.z,acc[1][2]); acc[1][3]=fmaf(a.y,w.w,acc[1][3]);
    acc[2][0]=fmaf(a.z,w.x,acc[2][0]); acc[2][1]=fmaf(a.z,w.y,acc[2][1]);
    acc[2][2]=fmaf(a.z,w.z,acc[2][2]); acc[2][3]=fmaf(a.z,w.w,acc[2][3]);
    acc[3][0]=fmaf(a.w,w.x,acc[3][0]); acc[3][1]=fmaf(a.w,w.y,acc[3][1]);
    acc[3][2]=fmaf(a.w,w.z,acc[3][2]); acc[3][3]=fmaf(a.w,w.w,acc[3][3]);
}

// ---------------- addressing GEMM: g_w[6144,64] = ktab[q] @ Mk^T -------------
__device__ void stage_addr(float* sm, const float* __restrict__ Mk,
                           const float* __restrict__ ktab, const int* __restrict__ q)
{
    float* As = sm + OFF_AS;      // [32][68]
    float* Ws = sm + OFF_WS;      // [32][36]
    float* part = sm + OFF_PART;  // [4][64][36]
    const int tid = threadIdx.x;
    const int s = tid >> 7, pos = tid & 127, rg = pos >> 3, cg = pos & 7;
    for (int tile = blockIdx.x; tile < 192; tile += NBLK) {
        const int row0 = (tile >> 1) * 64, cc0 = (tile & 1) * 32;
        float acc[4][4] = {};
#pragma unroll 1
        for (int ch = 0; ch < 16; ch++) {
            const int kb = ch * 32;
            {
                int rr = tid >> 3, kq = tid & 7;
                int qi = q[row0 + rr];
                float4 v = *(const float4*)(ktab + (size_t)qi * Dm + kb + kq * 4);
                float* a = As + (kq * 4) * 68 + rr;
                a[0] = v.x; a[68] = v.y; a[136] = v.z; a[204] = v.w;
            }
            if (tid < 256) {
                int n = tid >> 3, kq = tid & 7;
                float4 v = *(const float4*)(Mk + (size_t)(cc0 + n) * Dm + kb + kq * 4);
                float* w = Ws + (kq * 4) * 36 + n;
                w[0] = v.x; w[36] = v.y; w[72] = v.z; w[108] = v.w;
            }
            __syncthreads();
#pragma unroll
            for (int kk = 0; kk < 8; kk++) {
                int k = s * 8 + kk;
                float4 a4 = *(const float4*)(As + k * 68 + rg * 4);
                float4 w4 = *(const float4*)(Ws + k * 36 + cg * 4);
                fma16(acc, a4, w4);
            }
            __syncthreads();
        }
#pragma unroll
        for (int j = 0; j < 4; j++)
            *(float4*)(part + s * 2304 + (rg * 4 + j) * 36 + cg * 4) =
                make_float4(acc[j][0], acc[j][1], acc[j][2], acc[j][3]);
        __syncthreads();
        {
            int rr = tid >> 3, cgx = tid & 7;
            float4 v = make_float4(0.f, 0.f, 0.f, 0.f);
#pragma unroll
            for (int p = 0; p < 4; p++) {
                float4 u = *(const float4*)(part + p * 2304 + rr * 36 + cgx * 4);
                v.x += u.x; v.y += u.y; v.z += u.z; v.w += u.w;
            }
            *(float4*)(g_w + (size_t)(row0 + rr) * 64 + cc0 + cgx * 4) = v;
        }
        __syncthreads();
    }
}

// ---------------- softmax + triangular membership codes ----------------------
__device__ void stage_softmax(float* sm)
{
    unsigned char* ivb = (unsigned char*)(sm + OFF_WT);  // [16][64]
    const int wp = threadIdx.x >> 5, lane = threadIdx.x & 31;
    for (int rr = wp; rr < 48; rr += 16) {
        const int row = blockIdx.x * 48 + rr;
        float v0 = g_w[row * 64 + lane];
        float v1 = g_w[row * 64 + 32 + lane];
        float mx = fmaxf(v0, v1);
        for (int o = 16; o; o >>= 1) mx = fmaxf(mx, __shfl_xor_sync(0xffffffffu, mx, o));
        float e0 = expf(v0 - mx), e1 = expf(v1 - mx);
        float ss = e0 + e1;
        for (int o = 16; o; o >>= 1) ss += __shfl_xor_sync(0xffffffffu, ss, o);
        float inv = 1.0f / ss;
        float w0 = e0 * inv, w1 = e1 * inv;
        g_w[row * 64 + lane] = w0;
        g_w[row * 64 + 32 + lane] = w1;
        auto ivf = [](float w) -> int {
            float m = fmaxf(fminf((w - 0.075f) / (0.088f - 0.075f),
                                  (1.0f - w) / (1.0f - 0.088f)), 0.0f);
            return (m >= 0.6f) ? 2 : ((m >= 0.1f) ? 1 : 0);
        };
        ivb[wp * 64 + lane] = (unsigned char)ivf(w0);
        ivb[wp * 64 + 32 + lane] = (unsigned char)ivf(w1);
        __syncwarp();
        if (lane == 0) {
            unsigned long long c0 = 0ull, c1 = 0ull;
            for (int i = 0; i < 32; i++) {
                c0 |= (unsigned long long)ivb[wp * 64 + i] << (2 * i);
                c1 |= (unsigned long long)ivb[wp * 64 + 32 + i] << (2 * i);
            }
            g_code[row * 2] = c0;
            g_code[row * 2 + 1] = c1;
        }
        __syncwarp();
    }
}

// ---------------- src scan + memS / H0 / C0 / read_0 init --------------------
__device__ void stage_init(float* sm, const float* __restrict__ Mv0,
                           const float* __restrict__ hx0, const float* __restrict__ cx0,
                           int r0, int c0)
{
    float* memS = sm;
    float* wT = sm + OFF_WT;
    const int tid = threadIdx.x;
    if (tid < Tlen) {
        const int b = blockIdx.x, i = tid;
        unsigned long long cc0 = g_code[(b * Tlen + i) * 2];
        unsigned long long cc1 = g_code[(b * Tlen + i) * 2 + 1];
        int sv = i - 1;
        for (int j = i - 1; j >= 0; j--)
            if (g_code[(b * Tlen + j) * 2] == cc0 && g_code[(b * Tlen + j) * 2 + 1] == cc1) { sv = j; break; }
        g_src[b * Tlen + i] = sv;
    }
    for (int i = tid; i < 32768; i += NTHR) {
        int m = (i >> 5) & 63, cc = i & 31;
        memS[i] = Mv0[m * Dm + c0 + cc];
    }
    for (int i = tid; i < 1024; i += NTHR) {
        int bl = i >> 6, m = i & 63;
        wT[i] = g_w[((r0 + bl) * Tlen) * 64 + m];
    }
    __syncthreads();
    const int rr = tid >> 5, cc = tid & 31;
    const int b = r0 + rr, col = c0 + cc;
    g_H[(size_t)b * Dm + col] = hx0[col];
    g_C[(size_t)b * Dm + col] = cx0[col];
    float racc = 0.f;
#pragma unroll 4
    for (int m = 0; m < 64; m++)
        racc = fmaf(wT[rr * 64 + m], memS[(rr * 64 + m) * 32 + cc], racc);
    g_read[(size_t)b * Dm + col] = racc;
}

// ---------------- f / we GEMM (pipelined: cp.async W + reg-prefetch A) -------
template<int MODE>   // 0: f = tanh(.), X=g_read, tab=ktab ; 1: we = raw, X=g_f, tab=xtab
__device__ void stage_fwe(float* sm, const float* __restrict__ W, const float* __restrict__ bias,
                          const float* __restrict__ tab, const int* __restrict__ q,
                          const int* __restrict__ r, int t, int r0, int c0)
{
    float* As = sm + OFF_AS;
    float* part = sm + OFF_PART;
    int* sQ = (int*)(sm + OFF_I16);
    const int tid = threadIdx.x;
    const int g = tid >> 7, gt = tid & 127;
    const int s = gt >> 5, pos = gt & 31, rg = pos >> 3, cg = pos & 7;
    if (tid < 16) {
        int b = r0 + tid;
        int qi = q[b * Tlen + t];
        sQ[tid] = (MODE == 0) ? qi : (qi + 2000 * r[b * Tlen + t]);
    }
    __syncthreads();
    const float* X = (MODE == 0) ? g_read : g_f;

    // W cp.async tasks (2 per thread)
    const int n0 = (gt * 2) >> 3, kq0 = (gt * 2) & 7;
    const int n1 = (gt * 2 + 1) >> 3, kq1 = (gt * 2 + 1) & 7;
    float* wb0p = sm + OFF_WS + g * 1184;
    float* wb1p = part + g * 2304;
    unsigned wbu0 = (unsigned)__cvta_generic_to_shared(wb0p);
    unsigned wbu1 = (unsigned)__cvta_generic_to_shared(wb1p);
    const unsigned wo0 = (unsigned)(WOFF(n0) + kq0 * 4) * 4u;
    const unsigned wo1 = (unsigned)(WOFF(n1) + kq1 * 4) * 4u;
    int woff[4];
#pragma unroll
    for (int j = 0; j < 4; j++) { int c = cg * 4 + j; woff[j] = WOFF(c); }
    const int arr = gt >> 3, akq = gt & 7;

    // issue chunk 0 W + load chunk 0 A
    {
        int kb = g * 256;
        cpa16(wbu0 + wo0, W + (size_t)(c0 + n0) * 1024 + kb + kq0 * 4);
        cpa16(wbu0 + wo1, W + (size_t)(c0 + n1) * 1024 + kb + kq1 * 4);
        cpa_commit();
    }
    float4 aR;
    {
        int kb = g * 256;
        const float* srcp = (g < 2) ? X + (size_t)(r0 + arr) * Dm + kb + akq * 4
                                    : tab + (size_t)sQ[arr] * Dm + (kb - Dm) + akq * 4;
        aR = *(const float4*)srcp;
    }
    float acc[4][4] = {};
#pragma unroll 1
    for (int ch = 0; ch < 8; ch++) {
        if (ch < 7) {
            int kb = g * 256 + (ch + 1) * 32;
            unsigned wd = ((ch + 1) & 1) ? wbu1 : wbu0;
            cpa16(wd + wo0, W + (size_t)(c0 + n0) * 1024 + kb + kq0 * 4);
            cpa16(wd + wo1, W + (size_t)(c0 + n1) * 1024 + kb + kq1 * 4);
            cpa_commit();
        }
        {   // store A chunk ch (transposed k-major)
            float* a = As + g * 640 + (akq * 4) * 20 + arr;
            a[0] = aR.x; a[20] = aR.y; a[40] = aR.z; a[60] = aR.w;
        }
        float4 aN = aR;
        if (ch < 7) {
            int kb = g * 256 + (ch + 1) * 32;
            const float* srcp = (g < 2) ? X + (size_t)(r0 + arr) * Dm + kb + akq * 4
                                        : tab + (size_t)sQ[arr] * Dm + (kb - Dm) + akq * 4;
            aN = *(const float4*)srcp;
            cpa_wait1();
        } else {
            cpa_wait0();
        }
        barg(g);
        const float* Wb = (ch & 1) ? wb1p : wb0p;
#pragma unroll
        for (int kk = 0; kk < 8; kk++) {
            int k = s * 8 + kk;
            float4 a4 = *(const float4*)(As + g * 640 + k * 20 + rg * 4);
            float4 w4 = make_float4(Wb[woff[0] + k], Wb[woff[1] + k],
                                    Wb[woff[2] + k], Wb[woff[3] + k]);
            fma16(acc, a4, w4);
        }
        aR = aN;
        barg(g);
    }
    const int sid = g * 4 + s;
#pragma unroll
    for (int j = 0; j < 4; j++)
        *(float4*)(part + sid * 576 + (rg * 4 + j) * 36 + cg * 4) =
            make_float4(acc[j][0], acc[j][1], acc[j][2], acc[j][3]);
    __syncthreads();
    {
        const int rr = tid >> 5, cc = tid & 31;
        float v = 0.f;
#pragma unroll
        for (int p = 0; p < 16; p++) v += part[p * 576 + rr * 36 + cc];
        v += bias[c0 + cc];
        const int b = r0 + rr;
        if (MODE == 0) {
            v = tanhf(v);
            g_f[(size_t)b * Dm + c0 + cc] = v;
            g_ft[((size_t)t * Bsz + b) * Dm + c0 + cc] = v;
        } else {
            g_we[(size_t)b * Dm + c0 + cc] = v;
        }
    }
}

// ---------------- e/a GEMMs + smem memory update (pipelined) -----------------
__device__ void stage_ea(float* sm, const float* __restrict__ We, const float* __restrict__ be,
                         const float* __restrict__ Wa, const float* __restrict__ ba,
                         int t, int r0, int c0)
{
    float* memS = sm;
    float* As = sm + OFF_AS;
    float* part = sm + OFF_PART;
    float* wT = sm + OFF_WT;
    float* wN = sm + OFF_WN;
    const int tid = threadIdx.x;
    const int g = tid >> 7, gt = tid & 127;
    const int s = gt >> 5, pos = gt & 31, rg = pos >> 3, cg = pos & 7;
    for (int i = tid; i < 1024; i += NTHR) {
        int bl = i >> 6, m = i & 63;
        wT[i] = g_w[((r0 + bl) * Tlen + t) * 64 + m];
        wN[i] = (t + 1 < Tlen) ? g_w[((r0 + bl) * Tlen + t + 1) * 64 + m] : 0.0f;
    }
    __syncthreads();
    const float* W = (g < 2) ? We : Wa;

    const int n0 = (gt * 2) >> 3, kq0 = (gt * 2) & 7;
    const int n1 = (gt * 2 + 1) >> 3, kq1 = (gt * 2 + 1) & 7;
    float* wb0p = sm + OFF_WS + g * 1184;
    float* wb1p = part + g * 2304;
    unsigned wbu0 = (unsigned)__cvta_generic_to_shared(wb0p);
    unsigned wbu1 = (unsigned)__cvta_generic_to_shared(wb1p);
    const unsigned wo0 = (unsigned)(WOFF(n0) + kq0 * 4) * 4u;
    const unsigned wo1 = (unsigned)(WOFF(n1) + kq1 * 4) * 4u;
    int woff[4];
#pragma unroll
    for (int j = 0; j < 4; j++) { int c = cg * 4 + j; woff[j] = WOFF(c); }
    const int arr = gt >> 3, akq = gt & 7;
    const int kh = (g & 1) * 256;

    {
        cpa16(wbu0 + wo0, W + (size_t)(c0 + n0) * 512 + kh + kq0 * 4);
        cpa16(wbu0 + wo1, W + (size_t)(c0 + n1) * 512 + kh + kq1 * 4);
        cpa_commit();
    }
    float4 aR = *(const float4*)(g_we + (size_t)(r0 + arr) * Dm + kh + akq * 4);
    float acc[4][4] = {};
#pragma unroll 1
    for (int ch = 0; ch < 8; ch++) {
        if (ch < 7) {
            int kb = kh + (ch + 1) * 32;
            unsigned wd = ((ch + 1) & 1) ? wbu1 : wbu0;
            cpa16(wd + wo0, W + (size_t)(c0 + n0) * 512 + kb + kq0 * 4);
            cpa16(wd + wo1, W + (size_t)(c0 + n1) * 512 + kb + kq1 * 4);
            cpa_commit();
        }
        {
            float* a = As + g * 640 + (akq * 4) * 20 + arr;
            a[0] = aR.x; a[20] = aR.y; a[40] = aR.z; a[60] = aR.w;
        }
        float4 aN = aR;
        if (ch < 7) {
            int kb = kh + (ch + 1) * 32;
            aN = *(const float4*)(g_we + (size_t)(r0 + arr) * Dm + kb + akq * 4);
            cpa_wait1();
        } else {
            cpa_wait0();
        }
        barg(g);
        const float* Wb = (ch & 1) ? wb1p : wb0p;
#pragma unroll
        for (int kk = 0; kk < 8; kk++) {
            int k = s * 8 + kk;
            float4 a4 = *(const float4*)(As + g * 640 + k * 20 + rg * 4);
            float4 w4 = make_float4(Wb[woff[0] + k], Wb[woff[1] + k],
                                    Wb[woff[2] + k], Wb[woff[3] + k]);
            fma16(acc, a4, w4);
        }
        aR = aN;
        barg(g);
    }
    const int sid = g * 4 + s;
#pragma unroll
    for (int j = 0; j < 4; j++)
        *(float4*)(part + sid * 576 + (rg * 4 + j) * 36 + cg * 4) =
            make_float4(acc[j][0], acc[j][1], acc[j][2], acc[j][3]);
    __syncthreads();
    {
        const int rr = tid >> 5, cc = tid & 31;
        float ve = 0.f, va = 0.f;
#pragma unroll
        for (int p = 0; p < 8; p++)  ve += part[p * 576 + rr * 36 + cc];
#pragma unroll
        for (int p = 8; p < 16; p++) va += part[p * 576 + rr * 36 + cc];
        ve = sigm(ve + be[c0 + cc]);
        va = tanhf(va + ba[c0 + cc]);
        float racc = 0.f;
#pragma unroll 4
        for (int m = 0; m < 64; m++) {
            float wt = wT[rr * 64 + m], wn = wN[rr * 64 + m];
            float* p = &memS[(rr * 64 + m) * 32 + cc];
            float v = *p;
            v = v * (1.0f - wt * ve) + wt * va;
            *p = v;
            racc = fmaf(wn, v, racc);
        }
        g_read[(size_t)(r0 + rr) * Dm + c0 + cc] = racc;
    }
}

// ---------------- hop-LSTM step (pipelined, 32 chunks) -----------------------
__device__ void stage_lstm(float* sm, const float* __restrict__ Wih, const float* __restrict__ Whh,
                           const float* __restrict__ bih, const float* __restrict__ bhh,
                           int t, int r0, int c0)
{
    float* As = sm + OFF_AS;
    float* part = sm + OFF_PART;
    int* s16 = (int*)(sm + OFF_I16);
    const int tid = threadIdx.x;
    const int g = tid >> 7, gt = tid & 127;
    const int s = gt >> 5, pos = gt & 31, rg = pos >> 3, cg = pos & 7;
    if (tid < 16) s16[tid] = g_src[(r0 + tid) * Tlen + t] + 1;
    __syncthreads();

    const int n0 = (gt * 2) >> 3, kq0 = (gt * 2) & 7;
    const int n1 = (gt * 2 + 1) >> 3, kq1 = (gt * 2 + 1) & 7;
    float* wb0p = sm + OFF_WS + g * 1184;
    float* wb1p = part + g * 2304;
    unsigned wbu0 = (unsigned)__cvta_generic_to_shared(wb0p);
    unsigned wbu1 = (unsigned)__cvta_generic_to_shared(wb1p);
    const unsigned wo0 = (unsigned)(WOFF(n0) + kq0 * 4) * 4u;
    const unsigned wo1 = (unsigned)(WOFF(n1) + kq1 * 4) * 4u;
    int woff[4];
#pragma unroll
    for (int j = 0; j < 4; j++) { int c = cg * 4 + j; woff[j] = WOFF(c); }
    const int arr = gt >> 3, akq = gt & 7;
    // W row bases for this group's gate quarter
    const float* Wi0 = Wih + (size_t)(g * Dm + c0 + n0) * Dm + kq0 * 4;
    const float* Wi1 = Wih + (size_t)(g * Dm + c0 + n1) * Dm + kq1 * 4;
    const float* Wh0 = Whh + (size_t)(g * Dm + c0 + n0) * Dm + kq0 * 4;
    const float* Wh1 = Whh + (size_t)(g * Dm + c0 + n1) * Dm + kq1 * 4;
    const float* aF = g_ft + ((size_t)t * Bsz + r0 + arr) * Dm + akq * 4;
    const float* aH = g_H + ((size_t)s16[arr] * Bsz + r0 + arr) * Dm + akq * 4;

    {   // chunk 0
        cpa16(wbu0 + wo0, Wi0);
        cpa16(wbu0 + wo1, Wi1);
        cpa_commit();
    }
    float4 aR = *(const float4*)aF;
    float acc[4][4] = {};
#pragma unroll 1
    for (int ch = 0; ch < 32; ch++) {
        if (ch < 31) {
            int kb = (ch + 1) * 32;
            unsigned wd = ((ch + 1) & 1) ? wbu1 : wbu0;
            const float* s0 = (kb < Dm) ? Wi0 + kb : Wh0 + (kb - Dm);
            const float* s1 = (kb < Dm) ? Wi1 + kb : Wh1 + (kb - Dm);
            cpa16(wd + wo0, s0);
            cpa16(wd + wo1, s1);
            cpa_commit();
        }
        {
            float* a = As + g * 640 + (akq * 4) * 20 + arr;
            a[0] = aR.x; a[20] = aR.y; a[40] = aR.z; a[60] = aR.w;
        }
        float4 aN = aR;
        if (ch < 31) {
            int kb = (ch + 1) * 32;
            const float* srcp = (kb < Dm) ? aF + kb : aH + (kb - Dm);
            aN = *(const float4*)srcp;
            cpa_wait1();
        } else {
            cpa_wait0();
        }
        barg(g);
        const float* Wb = (ch & 1) ? wb1p : wb0p;
#pragma unroll
        for (int kk = 0; kk < 8; kk++) {
            int k = s * 8 + kk;
            float4 a4 = *(const float4*)(As + g * 640 + k * 20 + rg * 4);
            float4 w4 = make_float4(Wb[woff[0] + k], Wb[woff[1] + k],
                                    Wb[woff[2] + k], Wb[woff[3] + k]);
            fma16(acc, a4, w4);
        }
        aR = aN;
        barg(g);
    }
    const int sid = g * 4 + s;
#pragma unroll
    for (int j = 0; j < 4; j++)
        *(float4*)(part + sid * 576 + (rg * 4 + j) * 36 + cg * 4) =
            make_float4(acc[j][0], acc[j][1], acc[j][2], acc[j][3]);
    __syncthreads();
    {
        const int rr = tid >> 5, cc = tid & 31;
        float gi = 0.f, gf = 0.f, gg = 0.f, go = 0.f;
#pragma unroll
        for (int p = 0; p < 4; p++)   gi += part[p * 576 + rr * 36 + cc];
#pragma unroll
        for (int p = 4; p < 8; p++)   gf += part[p * 576 + rr * 36 + cc];
#pragma unroll
        for (int p = 8; p < 12; p++)  gg += part[p * 576 + rr * 36 + cc];
#pragma unroll
        for (int p = 12; p < 16; p++) go += part[p * 576 + rr * 36 + cc];
        const int b = r0 + rr, col = c0 + cc;
        gi += bih[col] + bhh[col];
        gf += bih[512 + col] + bhh[512 + col];
        gg += bih[1024 + col] + bhh[1024 + col];
        go += bih[1536 + col] + bhh[1536 + col];
        float cin = g_C[((size_t)s16[rr] * Bsz + b) * Dm + col];
        float cn = sigm(gf) * cin + sigm(gi) * tanhf(gg);
        float hn = sigm(go) * tanhf(cn);
        g_C[((size_t)(t + 1) * Bsz + b) * Dm + col] = cn;
        g_H[((size_t)(t + 1) * Bsz + b) * Dm + col] = hn;
    }
}

// ---------------- prediction head --------------------------------------------
__device__ void stage_head(const float* __restrict__ Wp, const float* __restrict__ bp,
                           float* __restrict__ out)
{
    const int wp = threadIdx.x >> 5, lane = threadIdx.x & 31;
    for (int bt = blockIdx.x * 16 + wp; bt < Bsz * Tlen; bt += NBLK * 16) {
        const int b = bt / Tlen, t = bt % Tlen;
        const float* h = &g_H[((size_t)(t + 1) * Bsz + b) * Dm];
        float s = 0.f;
        for (int i = lane; i < Dm; i += 32) s = fmaf(h[i], Wp[i], s);
        for (int o = 16; o; o >>= 1) s += __shfl_xor_sync(0xffffffffu, s, o);
        if (lane == 0) out[bt] = sigm(s + bp[0]);
    }
}

// ---------------- the single persistent kernel -------------------------------
__global__ void __launch_bounds__(NTHR, 1) k_persist(
    const int* __restrict__ q, const int* __restrict__ r,
    const float* __restrict__ Mk, const float* __restrict__ Mv0,
    const float* __restrict__ ktab, const float* __restrict__ xtab,
    const float* __restrict__ We, const float* __restrict__ be,
    const float* __restrict__ Wadd, const float* __restrict__ badd,
    const float* __restrict__ Wa, const float* __restrict__ ba,
    const float* __restrict__ Wf, const float* __restrict__ bf,
    const float* __restrict__ Wih, const float* __restrict__ Whh,
    const float* __restrict__ bih, const float* __restrict__ bhh,
    const float* __restrict__ hx0, const float* __restrict__ cx0,
    const float* __restrict__ Wp, const float* __restrict__ bp,
    float* __restrict__ out)
{
    extern __shared__ float sm[];
    const int grp = blockIdx.x & 7;
    const int grp32 = grp * 32;
    unsigned ls = 0, lsr = 0;
    if (threadIdx.x == 0) { ls = g_sense; lsr = g_gsense[grp32]; }
    const int r0 = grp * 16;
    const int c0 = (blockIdx.x >> 3) * 32;

    stage_addr(sm, Mk, ktab, q);                          gsync(ls);
    stage_softmax(sm);                                    gsync(ls);
    stage_init(sm, Mv0, hx0, cx0, r0, c0);                gsync(ls);

    for (int t = 0; t < Tlen; t++) {
        stage_fwe<0>(sm, Wf, bf, ktab, q, r, t, r0, c0);  gsync_grp(lsr, grp32);
        stage_fwe<1>(sm, Wa, ba, xtab, q, r, t, r0, c0);  gsync_grp(lsr, grp32);
        stage_ea(sm, We, be, Wadd, badd, t, r0, c0);      gsync_grp(lsr, grp32);
    }
    for (int t = 0; t < Tlen; t++) {
        stage_lstm(sm, Wih, Whh, bih, bhh, t, r0, c0);    gsync_grp(lsr, grp32);
    }
    gsync(ls);                                            // head reads all rows
    stage_head(Wp, bp, out);
}

// ----------------------------------------------------------------------------
extern "C" void kernel_launch(void* const* d_in, const int* in_sizes, int n_in,
                              void* d_out, int out_size)
{
    const int*   q    = (const int*)d_in[0];
    const int*   r    = (const int*)d_in[1];
    const float* Mk   = (const float*)d_in[2];
    const float* Mv0  = (const float*)d_in[3];
    const float* ktab = (const float*)d_in[4];
    const float* xtab = (const float*)d_in[5];
    const float* We   = (const float*)d_in[6];
    const float* be   = (const float*)d_in[7];
    const float* Wadd = (const float*)d_in[8];
    const float* badd = (const float*)d_in[9];
    const float* Wa   = (const float*)d_in[10];
    const float* ba   = (const float*)d_in[11];
    const float* Wf   = (const float*)d_in[12];
    const float* bf   = (const float*)d_in[13];
    const float* Wih  = (const float*)d_in[14];
    const float* Whh  = (const float*)d_in[15];
    const float* bih  = (const float*)d_in[16];
    const float* bhh  = (const float*)d_in[17];
    const float* hx0  = (const float*)d_in[18];
    const float* cx0  = (const float*)d_in[19];
    const float* Wp   = (const float*)d_in[20];
    const float* bp   = (const float*)d_in[21];
    float* out = (float*)d_out;

    static bool attr_set = false;
    if (!attr_set) {
        cudaFuncSetAttribute(k_persist, cudaFuncAttributeMaxDynamicSharedMemorySize, SMEM_BYTES);
        attr_set = true;
    }
    k_persist<<<NBLK, NTHR, SMEM_BYTES>>>(q, r, Mk, Mv0, ktab, xtab, We, be, Wadd, badd,
                                          Wa, ba, Wf, bf, Wih, Whh, bih, bhh,
                                          hx0, cx0, Wp, bp, out);
}

// round 13
// speedup vs baseline: 1.3673x; 1.0187x over previous
#include <cuda_runtime.h>
#include <math.h>

#define Bsz 128
#define Tlen 48
#define Dm 512
#define NBLK 128
#define NTHR 512

// ---------------- global scratch ---------------------------------------------
__device__ float g_w[Bsz*Tlen*64];
__device__ unsigned long long g_code[Bsz*Tlen*2];
__device__ int g_src[Bsz*Tlen];
__device__ float g_read[Bsz*Dm];
__device__ float g_f[Bsz*Dm];
__device__ float g_we[Bsz*Dm];
__device__ float g_ft[Tlen*Bsz*Dm];
__device__ float g_H[(Tlen+1)*Bsz*Dm];
__device__ float g_C[(Tlen+1)*Bsz*Dm];
// k-major weight slabs (built once per launch by stage_wtr)
__device__ float g_WTf[16*1024*32];    // [cg][k][n]  Wf
__device__ float g_WTa2[16*1024*32];   // [cg][k][n]  Wa
__device__ float g_WTe[16*512*32];     // [cg][k][n]  We
__device__ float g_WTad[16*512*32];    // [cg][k][n]  Wadd
__device__ float g_WTl[16*4*1024*32];  // [cg][gate][k(ih|hh)][n]
// barriers: monotonic counters (graph-replay safe)
__device__ unsigned g_count = 0;
__device__ volatile unsigned g_sense = 0;
__device__ unsigned g_gcnt[8*32];
__device__ volatile unsigned g_gsense[8*32];

__device__ __forceinline__ float sigm(float x) { return 1.0f / (1.0f + expf(-x)); }

// per-warp-group (128-thread) named barrier: ids 1..4
__device__ __forceinline__ void barg(int g) {
    asm volatile("bar.sync %0, 128;" :: "r"(g + 1) : "memory");
}

// smem layout (floats):
// [0,32768) memS (ALSO reused by lstm phase: W bufs 4x2x2304 at g*4608, A 4x1280 at 18432+g*1280)
// AS 4x640 | WS 4x1184 (W buf0) | PART 16x576 (fwe/ea overlay W buf1 at g*2304) | wT | wN | i16
#define OFF_AS   32768
#define OFF_WS   35328
#define OFF_PART 40064
#define OFF_WT   49280
#define OFF_WN   50304
#define OFF_I16  51328
#define SMEM_FLOATS 51344
#define SMEM_BYTES (SMEM_FLOATS * 4)

// ---------------- cp.async helpers --------------------------------------------
__device__ __forceinline__ void cpa16(unsigned dst, const float* src) {
    asm volatile("cp.async.cg.shared.global [%0], [%1], 16;" :: "r"(dst), "l"(src));
}
__device__ __forceinline__ void cpa_commit() {
    asm volatile("cp.async.commit_group;" ::: "memory");
}
__device__ __forceinline__ void cpa_wait1() {
    asm volatile("cp.async.wait_group 1;" ::: "memory");
}
__device__ __forceinline__ void cpa_wait0() {
    asm volatile("cp.async.wait_group 0;" ::: "memory");
}

// ---------------- global grid barrier -----------------------------------------
__device__ __forceinline__ void gsync(unsigned& ls) {
    __syncthreads();
    if (threadIdx.x == 0) {
        unsigned target = ls + 1u;
        __threadfence();
        unsigned a = atomicAdd(&g_count, 1u) + 1u;
        if (a == target * (unsigned)NBLK) g_sense = target;
        while (g_sense != target) { }
        ls = target;
        __threadfence();
    }
    __syncthreads();
}

// ---------------- group barrier: 16 blocks sharing one row-group --------------
__device__ __forceinline__ void gsync_grp(unsigned& ls, int grp32) {
    __syncthreads();
    if (threadIdx.x == 0) {
        unsigned target = ls + 1u;
        __threadfence();
        unsigned a = atomicAdd(&g_gcnt[grp32], 1u) + 1u;
        if (a == target * 16u) g_gsense[grp32] = target;
        while (g_gsense[grp32] != target) { }
        ls = target;
        __threadfence();
    }
    __syncthreads();
}

__device__ __forceinline__ void fma16(float (&acc)[4][4], float4 a, float4 w) {
    acc[0][0]=fmaf(a.x,w.x,acc[0][0]); acc[0][1]=fmaf(a.x,w.y,acc[0][1]);
    acc[0][2]=fmaf(a.x,w.z,acc[0][2]); acc[0][3]=fmaf(a.x,w.w,acc[0][3]);
    acc[1][0]=fmaf(a.y,w.x,acc[1][0]); acc[1][1]=fmaf(a.y,w.y,acc[1][1]);
    acc[1][2]=fmaf(a.y,w.z,acc[1][2]); acc[1][3]=fmaf(a.y,w.w,acc[1][3]);
    acc[2][0]=fmaf(a.z,w.x,acc[2][0]); acc[2][1]=fmaf(a.z,w.y,acc[2][1]);
    acc[2][2]=fmaf(a.z,w.z,acc[2][2]); acc[2][3]=fmaf(a.z,w.w,acc[2][3]);
    acc[3][0]=fmaf(a.w,w.x,acc[3][0]); acc[3][1]=fmaf(a.w,w.y,acc[3][1]);
    acc[3][2]=fmaf(a.w,w.z,acc[3][2]); acc[3][3]=fmaf(a.w,w.w,acc[3][3]);
}

// ---------------- one-time k-major weight transposes --------------------------
__device__ void stage_wtr(const float* __restrict__ Wf, const float* __restrict__ Wa,
                          const float* __restrict__ We, const float* __restrict__ Wadd,
                          const float* __restrict__ Wih, const float* __restrict__ Whh)
{
    const int gid = blockIdx.x * NTHR + threadIdx.x;
    const int gs = NBLK * NTHR;   // 65536
    for (int d = gid; d < 16*1024*32; d += gs) {
        int cg = d >> 15, n = (d >> 10) & 31, k = d & 1023;
        int dst = (cg << 15) + k * 32 + n;
        g_WTf[dst]  = Wf[(size_t)(cg * 32 + n) * 1024 + k];
        g_WTa2[dst] = Wa[(size_t)(cg * 32 + n) * 1024 + k];
    }
    for (int d = gid; d < 16*512*32; d += gs) {
        int cg = d >> 14, n = (d >> 9) & 31, k = d & 511;
        int dst = (cg << 14) + k * 32 + n;
        g_WTe[dst]  = We[(size_t)(cg * 32 + n) * 512 + k];
        g_WTad[dst] = Wadd[(size_t)(cg * 32 + n) * 512 + k];
    }
    for (int d = gid; d < 16*4*1024*32; d += gs) {
        int cg = d >> 17, gate = (d >> 15) & 3, n = (d >> 10) & 31, k = d & 1023;
        int dst = ((cg * 4 + gate) << 15) + k * 32 + n;
        g_WTl[dst] = (k < 512)
            ? Wih[(size_t)(gate * 512 + cg * 32 + n) * 512 + k]
            : Whh[(size_t)(gate * 512 + cg * 32 + n) * 512 + (k - 512)];
    }
}

// ---------------- addressing GEMM: g_w[6144,64] = ktab[q] @ Mk^T -------------
__device__ void stage_addr(float* sm, const float* __restrict__ Mk,
                           const float* __restrict__ ktab, const int* __restrict__ q)
{
    float* As = sm + OFF_AS;      // [32][68]
    float* Ws = sm + OFF_WS;      // [32][36]
    float* part = sm + OFF_PART;  // [4][64][36]
    const int tid = threadIdx.x;
    const int s = tid >> 7, pos = tid & 127, rg = pos >> 3, cg = pos & 7;
    for (int tile = blockIdx.x; tile < 192; tile += NBLK) {
        const int row0 = (tile >> 1) * 64, cc0 = (tile & 1) * 32;
        float acc[4][4] = {};
#pragma unroll 1
        for (int ch = 0; ch < 16; ch++) {
            const int kb = ch * 32;
            {
                int rr = tid >> 3, kq = tid & 7;
                int qi = q[row0 + rr];
                float4 v = *(const float4*)(ktab + (size_t)qi * Dm + kb + kq * 4);
                float* a = As + (kq * 4) * 68 + rr;
                a[0] = v.x; a[68] = v.y; a[136] = v.z; a[204] = v.w;
            }
            if (tid < 256) {
                int n = tid >> 3, kq = tid & 7;
                float4 v = *(const float4*)(Mk + (size_t)(cc0 + n) * Dm + kb + kq * 4);
                float* w = Ws + (kq * 4) * 36 + n;
                w[0] = v.x; w[36] = v.y; w[72] = v.z; w[108] = v.w;
            }
            __syncthreads();
#pragma unroll
            for (int kk = 0; kk < 8; kk++) {
                int k = s * 8 + kk;
                float4 a4 = *(const float4*)(As + k * 68 + rg * 4);
                float4 w4 = *(const float4*)(Ws + k * 36 + cg * 4);
                fma16(acc, a4, w4);
            }
            __syncthreads();
        }
#pragma unroll
        for (int j = 0; j < 4; j++)
            *(float4*)(part + s * 2304 + (rg * 4 + j) * 36 + cg * 4) =
                make_float4(acc[j][0], acc[j][1], acc[j][2], acc[j][3]);
        __syncthreads();
        {
            int rr = tid >> 3, cgx = tid & 7;
            float4 v = make_float4(0.f, 0.f, 0.f, 0.f);
#pragma unroll
            for (int p = 0; p < 4; p++) {
                float4 u = *(const float4*)(part + p * 2304 + rr * 36 + cgx * 4);
                v.x += u.x; v.y += u.y; v.z += u.z; v.w += u.w;
            }
            *(float4*)(g_w + (size_t)(row0 + rr) * 64 + cc0 + cgx * 4) = v;
        }
        __syncthreads();
    }
}

// ---------------- softmax + triangular membership codes ----------------------
__device__ void stage_softmax(float* sm)
{
    unsigned char* ivb = (unsigned char*)(sm + OFF_WT);  // [16][64]
    const int wp = threadIdx.x >> 5, lane = threadIdx.x & 31;
    for (int rr = wp; rr < 48; rr += 16) {
        const int row = blockIdx.x * 48 + rr;
        float v0 = g_w[row * 64 + lane];
        float v1 = g_w[row * 64 + 32 + lane];
        float mx = fmaxf(v0, v1);
        for (int o = 16; o; o >>= 1) mx = fmaxf(mx, __shfl_xor_sync(0xffffffffu, mx, o));
        float e0 = expf(v0 - mx), e1 = expf(v1 - mx);
        float ss = e0 + e1;
        for (int o = 16; o; o >>= 1) ss += __shfl_xor_sync(0xffffffffu, ss, o);
        float inv = 1.0f / ss;
        float w0 = e0 * inv, w1 = e1 * inv;
        g_w[row * 64 + lane] = w0;
        g_w[row * 64 + 32 + lane] = w1;
        auto ivf = [](float w) -> int {
            float m = fmaxf(fminf((w - 0.075f) / (0.088f - 0.075f),
                                  (1.0f - w) / (1.0f - 0.088f)), 0.0f);
            return (m >= 0.6f) ? 2 : ((m >= 0.1f) ? 1 : 0);
        };
        ivb[wp * 64 + lane] = (unsigned char)ivf(w0);
        ivb[wp * 64 + 32 + lane] = (unsigned char)ivf(w1);
        __syncwarp();
        if (lane == 0) {
            unsigned long long c0 = 0ull, c1 = 0ull;
            for (int i = 0; i < 32; i++) {
                c0 |= (unsigned long long)ivb[wp * 64 + i] << (2 * i);
                c1 |= (unsigned long long)ivb[wp * 64 + 32 + i] << (2 * i);
            }
            g_code[row * 2] = c0;
            g_code[row * 2 + 1] = c1;
        }
        __syncwarp();
    }
}

// ---------------- src scan + memS / H0 / C0 / read_0 init --------------------
__device__ void stage_init(float* sm, const float* __restrict__ Mv0,
                           const float* __restrict__ hx0, const float* __restrict__ cx0,
                           int r0, int c0)
{
    float* memS = sm;
    float* wT = sm + OFF_WT;
    const int tid = threadIdx.x;
    if (tid < Tlen) {
        const int b = blockIdx.x, i = tid;
        unsigned long long cc0 = g_code[(b * Tlen + i) * 2];
        unsigned long long cc1 = g_code[(b * Tlen + i) * 2 + 1];
        int sv = i - 1;
        for (int j = i - 1; j >= 0; j--)
            if (g_code[(b * Tlen + j) * 2] == cc0 && g_code[(b * Tlen + j) * 2 + 1] == cc1) { sv = j; break; }
        g_src[b * Tlen + i] = sv;
    }
    for (int i = tid; i < 32768; i += NTHR) {
        int m = (i >> 5) & 63, cc = i & 31;
        memS[i] = Mv0[m * Dm + c0 + cc];
    }
    for (int i = tid; i < 1024; i += NTHR) {
        int bl = i >> 6, m = i & 63;
        wT[i] = g_w[((r0 + bl) * Tlen) * 64 + m];
    }
    __syncthreads();
    const int rr = tid >> 5, cc = tid & 31;
    const int b = r0 + rr, col = c0 + cc;
    g_H[(size_t)b * Dm + col] = hx0[col];
    g_C[(size_t)b * Dm + col] = cx0[col];
    float racc = 0.f;
#pragma unroll 4
    for (int m = 0; m < 64; m++)
        racc = fmaf(wT[rr * 64 + m], memS[(rr * 64 + m) * 32 + cc], racc);
    g_read[(size_t)b * Dm + col] = racc;
}

// ---------------- f / we GEMM (pipelined, k-major W slab, LDS.128 W) ---------
template<int MODE>   // 0: f = tanh(.), X=g_read, tab=ktab ; 1: we = raw, X=g_f, tab=xtab
__device__ void stage_fwe(float* sm, const float* __restrict__ bias,
                          const float* __restrict__ tab, const int* __restrict__ q,
                          const int* __restrict__ r, int t, int r0, int c0)
{
    float* As = sm + OFF_AS;
    float* part = sm + OFF_PART;
    int* sQ = (int*)(sm + OFF_I16);
    const int tid = threadIdx.x;
    const int g = tid >> 7, gt = tid & 127;
    const int s = gt >> 5, pos = gt & 31, rg = pos >> 3, cg = pos & 7;
    if (tid < 16) {
        int b = r0 + tid;
        int qi = q[b * Tlen + t];
        sQ[tid] = (MODE == 0) ? qi : (qi + 2000 * r[b * Tlen + t]);
    }
    __syncthreads();
    const float* X = (MODE == 0) ? g_read : g_f;
    const float* slab = ((MODE == 0) ? g_WTf : g_WTa2) + ((size_t)(c0 >> 5) << 15);

    const int wk0 = (gt * 2) >> 3, wsg0 = (gt * 2) & 7;
    const int wk1 = (gt * 2 + 1) >> 3, wsg1 = (gt * 2 + 1) & 7;
    float* wb0p = sm + OFF_WS + g * 1184;
    float* wb1p = part + g * 2304;
    unsigned wbu0 = (unsigned)__cvta_generic_to_shared(wb0p);
    unsigned wbu1 = (unsigned)__cvta_generic_to_shared(wb1p);
    const unsigned wo0 = (unsigned)(wk0 * 36 + wsg0 * 4) * 4u;
    const unsigned wo1 = (unsigned)(wk1 * 36 + wsg1 * 4) * 4u;
    const int arr = gt >> 3, akq = gt & 7;

    {
        int kb = g * 256;
        cpa16(wbu0 + wo0, slab + (size_t)(kb + wk0) * 32 + wsg0 * 4);
        cpa16(wbu0 + wo1, slab + (size_t)(kb + wk1) * 32 + wsg1 * 4);
        cpa_commit();
    }
    float4 aR;
    {
        int kb = g * 256;
        const float* srcp = (g < 2) ? X + (size_t)(r0 + arr) * Dm + kb + akq * 4
                                    : tab + (size_t)sQ[arr] * Dm + (kb - Dm) + akq * 4;
        aR = *(const float4*)srcp;
    }
    float acc[4][4] = {};
#pragma unroll 1
    for (int ch = 0; ch < 8; ch++) {
        if (ch < 7) {
            int kb = g * 256 + (ch + 1) * 32;
            unsigned wd = ((ch + 1) & 1) ? wbu1 : wbu0;
            cpa16(wd + wo0, slab + (size_t)(kb + wk0) * 32 + wsg0 * 4);
            cpa16(wd + wo1, slab + (size_t)(kb + wk1) * 32 + wsg1 * 4);
            cpa_commit();
        }
        {
            float* a = As + g * 640 + (akq * 4) * 20 + arr;
            a[0] = aR.x; a[20] = aR.y; a[40] = aR.z; a[60] = aR.w;
        }
        float4 aN = aR;
        if (ch < 7) {
            int kb = g * 256 + (ch + 1) * 32;
            const float* srcp = (g < 2) ? X + (size_t)(r0 + arr) * Dm + kb + akq * 4
                                        : tab + (size_t)sQ[arr] * Dm + (kb - Dm) + akq * 4;
            aN = *(const float4*)srcp;
            cpa_wait1();
        } else {
            cpa_wait0();
        }
        barg(g);
        const float* Wb = (ch & 1) ? wb1p : wb0p;
#pragma unroll
        for (int kk = 0; kk < 8; kk++) {
            int k = s * 8 + kk;
            float4 a4 = *(const float4*)(As + g * 640 + k * 20 + rg * 4);
            float4 w4 = *(const float4*)(Wb + k * 36 + cg * 4);
            fma16(acc, a4, w4);
        }
        aR = aN;
        barg(g);
    }
    const int sid = g * 4 + s;
#pragma unroll
    for (int j = 0; j < 4; j++)
        *(float4*)(part + sid * 576 + (rg * 4 + j) * 36 + cg * 4) =
            make_float4(acc[j][0], acc[j][1], acc[j][2], acc[j][3]);
    __syncthreads();
    {
        const int rr = tid >> 5, cc = tid & 31;
        float v = 0.f;
#pragma unroll
        for (int p = 0; p < 16; p++) v += part[p * 576 + rr * 36 + cc];
        v += bias[c0 + cc];
        const int b = r0 + rr;
        if (MODE == 0) {
            v = tanhf(v);
            g_f[(size_t)b * Dm + c0 + cc] = v;
            g_ft[((size_t)t * Bsz + b) * Dm + c0 + cc] = v;
        } else {
            g_we[(size_t)b * Dm + c0 + cc] = v;
        }
    }
}

// ---------------- e/a GEMMs + smem memory update (pipelined, slab W) ---------
__device__ void stage_ea(float* sm, const float* __restrict__ be,
                         const float* __restrict__ ba, int t, int r0, int c0)
{
    float* memS = sm;
    float* As = sm + OFF_AS;
    float* part = sm + OFF_PART;
    float* wT = sm + OFF_WT;
    float* wN = sm + OFF_WN;
    const int tid = threadIdx.x;
    const int g = tid >> 7, gt = tid & 127;
    const int s = gt >> 5, pos = gt & 31, rg = pos >> 3, cg = pos & 7;
    for (int i = tid; i < 1024; i += NTHR) {
        int bl = i >> 6, m = i & 63;
        wT[i] = g_w[((r0 + bl) * Tlen + t) * 64 + m];
        wN[i] = (t + 1 < Tlen) ? g_w[((r0 + bl) * Tlen + t + 1) * 64 + m] : 0.0f;
    }
    __syncthreads();
    const float* slab = ((g < 2) ? g_WTe : g_WTad) + ((size_t)(c0 >> 5) << 14);

    const int wk0 = (gt * 2) >> 3, wsg0 = (gt * 2) & 7;
    const int wk1 = (gt * 2 + 1) >> 3, wsg1 = (gt * 2 + 1) & 7;
    float* wb0p = sm + OFF_WS + g * 1184;
    float* wb1p = part + g * 2304;
    unsigned wbu0 = (unsigned)__cvta_generic_to_shared(wb0p);
    unsigned wbu1 = (unsigned)__cvta_generic_to_shared(wb1p);
    const unsigned wo0 = (unsigned)(wk0 * 36 + wsg0 * 4) * 4u;
    const unsigned wo1 = (unsigned)(wk1 * 36 + wsg1 * 4) * 4u;
    const int arr = gt >> 3, akq = gt & 7;
    const int kh = (g & 1) * 256;

    {
        cpa16(wbu0 + wo0, slab + (size_t)(kh + wk0) * 32 + wsg0 * 4);
        cpa16(wbu0 + wo1, slab + (size_t)(kh + wk1) * 32 + wsg1 * 4);
        cpa_commit();
    }
    float4 aR = *(const float4*)(g_we + (size_t)(r0 + arr) * Dm + kh + akq * 4);
    float acc[4][4] = {};
#pragma unroll 1
    for (int ch = 0; ch < 8; ch++) {
        if (ch < 7) {
            int kb = kh + (ch + 1) * 32;
            unsigned wd = ((ch + 1) & 1) ? wbu1 : wbu0;
            cpa16(wd + wo0, slab + (size_t)(kb + wk0) * 32 + wsg0 * 4);
            cpa16(wd + wo1, slab + (size_t)(kb + wk1) * 32 + wsg1 * 4);
            cpa_commit();
        }
        {
            float* a = As + g * 640 + (akq * 4) * 20 + arr;
            a[0] = aR.x; a[20] = aR.y; a[40] = aR.z; a[60] = aR.w;
        }
        float4 aN = aR;
        if (ch < 7) {
            int kb = kh + (ch + 1) * 32;
            aN = *(const float4*)(g_we + (size_t)(r0 + arr) * Dm + kb + akq * 4);
            cpa_wait1();
        } else {
            cpa_wait0();
        }
        barg(g);
        const float* Wb = (ch & 1) ? wb1p : wb0p;
#pragma unroll
        for (int kk = 0; kk < 8; kk++) {
            int k = s * 8 + kk;
            float4 a4 = *(const float4*)(As + g * 640 + k * 20 + rg * 4);
            float4 w4 = *(const float4*)(Wb + k * 36 + cg * 4);
            fma16(acc, a4, w4);
        }
        aR = aN;
        barg(g);
    }
    const int sid = g * 4 + s;
#pragma unroll
    for (int j = 0; j < 4; j++)
        *(float4*)(part + sid * 576 + (rg * 4 + j) * 36 + cg * 4) =
            make_float4(acc[j][0], acc[j][1], acc[j][2], acc[j][3]);
    __syncthreads();
    {
        const int rr = tid >> 5, cc = tid & 31;
        float ve = 0.f, va = 0.f;
#pragma unroll
        for (int p = 0; p < 8; p++)  ve += part[p * 576 + rr * 36 + cc];
#pragma unroll
        for (int p = 8; p < 16; p++) va += part[p * 576 + rr * 36 + cc];
        ve = sigm(ve + be[c0 + cc]);
        va = tanhf(va + ba[c0 + cc]);
        float racc = 0.f;
#pragma unroll 4
        for (int m = 0; m < 64; m++) {
            float wt = wT[rr * 64 + m], wn = wN[rr * 64 + m];
            float* p = &memS[(rr * 64 + m) * 32 + cc];
            float v = *p;
            v = v * (1.0f - wt * ve) + wt * va;
            *p = v;
            racc = fmaf(wn, v, racc);
        }
        g_read[(size_t)(r0 + rr) * Dm + c0 + cc] = racc;
    }
}

// ---------------- hop-LSTM step (16 x 64-k chunks, bufs in memS region) ------
__device__ void stage_lstm(float* sm, const float* __restrict__ bih,
                           const float* __restrict__ bhh, int t, int r0, int c0)
{
    float* part = sm + OFF_PART;
    int* s16 = (int*)(sm + OFF_I16);
    const int tid = threadIdx.x;
    const int g = tid >> 7, gt = tid & 127;
    const int s = gt >> 5, pos = gt & 31, rg = pos >> 3, cg = pos & 7;
    if (tid < 16) s16[tid] = g_src[(r0 + tid) * Tlen + t] + 1;
    __syncthreads();

    const float* slab = g_WTl + ((size_t)((c0 >> 5) * 4 + g) << 15);
    // W cp.async: 4 tasks per thread (64 rows x 8 segs)
    int wk[4], wsg[4]; unsigned wo[4];
#pragma unroll
    for (int h = 0; h < 4; h++) {
        int i = gt * 4 + h;
        wk[h] = i >> 3; wsg[h] = i & 7;
        wo[h] = (unsigned)(wk[h] * 36 + wsg[h] * 4) * 4u;
    }
    float* wbL0 = sm + g * 4608;
    float* wbL1 = sm + g * 4608 + 2304;
    unsigned wbu0 = (unsigned)__cvta_generic_to_shared(wbL0);
    unsigned wbu1 = (unsigned)__cvta_generic_to_shared(wbL1);
    float* aLp = sm + 18432 + g * 1280;
    const int arr = gt >> 3, akq = gt & 7;
    const float* aF = g_ft + ((size_t)t * Bsz + r0 + arr) * Dm + akq * 4;
    const float* aH = g_H + ((size_t)s16[arr] * Bsz + r0 + arr) * Dm + akq * 4;

    {   // chunk 0
#pragma unroll
        for (int h = 0; h < 4; h++)
            cpa16(wbu0 + wo[h], slab + (size_t)wk[h] * 32 + wsg[h] * 4);
        cpa_commit();
    }
    float4 aR0 = *(const float4*)aF;
    float4 aR1 = *(const float4*)(aF + 32);
    float acc[4][4] = {};
#pragma unroll 1
    for (int ch = 0; ch < 16; ch++) {
        if (ch < 15) {
            int kb = (ch + 1) * 64;
            unsigned wd = ((ch + 1) & 1) ? wbu1 : wbu0;
#pragma unroll
            for (int h = 0; h < 4; h++)
                cpa16(wd + wo[h], slab + (size_t)(kb + wk[h]) * 32 + wsg[h] * 4);
            cpa_commit();
        }
        {   // store A chunk ch (k-major, k local 0..63)
            float* a = aLp + (akq * 4) * 20 + arr;
            a[0] = aR0.x; a[20] = aR0.y; a[40] = aR0.z; a[60] = aR0.w;
            float* a2 = aLp + (32 + akq * 4) * 20 + arr;
            a2[0] = aR1.x; a2[20] = aR1.y; a2[40] = aR1.z; a2[60] = aR1.w;
        }
        float4 aN0 = aR0, aN1 = aR1;
        if (ch < 15) {
            int kb = (ch + 1) * 64;   // chunks 0-7 -> ft (k<512), 8-15 -> H
            const float* basep = (kb < Dm) ? aF + kb : aH + (kb - Dm);
            aN0 = *(const float4*)basep;
            aN1 = *(const float4*)(basep + 32);
            cpa_wait1();
        } else {
            cpa_wait0();
        }
        barg(g);
        const float* Wb = (ch & 1) ? wbL1 : wbL0;
#pragma unroll
        for (int kk = 0; kk < 16; kk++) {
            int k = s * 16 + kk;
            float4 a4 = *(const float4*)(aLp + k * 20 + rg * 4);
            float4 w4 = *(const float4*)(Wb + k * 36 + cg * 4);
            fma16(acc, a4, w4);
        }
        aR0 = aN0; aR1 = aN1;
        barg(g);
    }
    const int sid = g * 4 + s;
#pragma unroll
    for (int j = 0; j < 4; j++)
        *(float4*)(part + sid * 576 + (rg * 4 + j) * 36 + cg * 4) =
            make_float4(acc[j][0], acc[j][1], acc[j][2], acc[j][3]);
    __syncthreads();
    {
        const int rr = tid >> 5, cc = tid & 31;
        float gi = 0.f, gf = 0.f, gg = 0.f, go = 0.f;
#pragma unroll
        for (int p = 0; p < 4; p++)   gi += part[p * 576 + rr * 36 + cc];
#pragma unroll
        for (int p = 4; p < 8; p++)   gf += part[p * 576 + rr * 36 + cc];
#pragma unroll
        for (int p = 8; p < 12; p++)  gg += part[p * 576 + rr * 36 + cc];
#pragma unroll
        for (int p = 12; p < 16; p++) go += part[p * 576 + rr * 36 + cc];
        const int b = r0 + rr, col = c0 + cc;
        gi += bih[col] + bhh[col];
        gf += bih[512 + col] + bhh[512 + col];
        gg += bih[1024 + col] + bhh[1024 + col];
        go += bih[1536 + col] + bhh[1536 + col];
        float cin = g_C[((size_t)s16[rr] * Bsz + b) * Dm + col];
        float cn = sigm(gf) * cin + sigm(gi) * tanhf(gg);
        float hn = sigm(go) * tanhf(cn);
        g_C[((size_t)(t + 1) * Bsz + b) * Dm + col] = cn;
        g_H[((size_t)(t + 1) * Bsz + b) * Dm + col] = hn;
    }
}

// ---------------- prediction head --------------------------------------------
__device__ void stage_head(const float* __restrict__ Wp, const float* __restrict__ bp,
                           float* __restrict__ out)
{
    const int wp = threadIdx.x >> 5, lane = threadIdx.x & 31;
    for (int bt = blockIdx.x * 16 + wp; bt < Bsz * Tlen; bt += NBLK * 16) {
        const int b = bt / Tlen, t = bt % Tlen;
        const float* h = &g_H[((size_t)(t + 1) * Bsz + b) * Dm];
        float s = 0.f;
        for (int i = lane; i < Dm; i += 32) s = fmaf(h[i], Wp[i], s);
        for (int o = 16; o; o >>= 1) s += __shfl_xor_sync(0xffffffffu, s, o);
        if (lane == 0) out[bt] = sigm(s + bp[0]);
    }
}

// ---------------- the single persistent kernel -------------------------------
__global__ void __launch_bounds__(NTHR, 1) k_persist(
    const int* __restrict__ q, const int* __restrict__ r,
    const float* __restrict__ Mk, const float* __restrict__ Mv0,
    const float* __restrict__ ktab, const float* __restrict__ xtab,
    const float* __restrict__ We, const float* __restrict__ be,
    const float* __restrict__ Wadd, const float* __restrict__ badd,
    const float* __restrict__ Wa, const float* __restrict__ ba,
    const float* __restrict__ Wf, const float* __restrict__ bf,
    const float* __restrict__ Wih, const float* __restrict__ Whh,
    const float* __restrict__ bih, const float* __restrict__ bhh,
    const float* __restrict__ hx0, const float* __restrict__ cx0,
    const float* __restrict__ Wp, const float* __restrict__ bp,
    float* __restrict__ out)
{
    extern __shared__ float sm[];
    const int grp = blockIdx.x & 7;
    const int grp32 = grp * 32;
    unsigned ls = 0, lsr = 0;
    if (threadIdx.x == 0) { ls = g_sense; lsr = g_gsense[grp32]; }
    const int r0 = grp * 16;
    const int c0 = (blockIdx.x >> 3) * 32;

    stage_wtr(Wf, Wa, We, Wadd, Wih, Whh);
    stage_addr(sm, Mk, ktab, q);                          gsync(ls);
    stage_softmax(sm);                                    gsync(ls);
    stage_init(sm, Mv0, hx0, cx0, r0, c0);                gsync(ls);

    for (int t = 0; t < Tlen; t++) {
        stage_fwe<0>(sm, bf, ktab, q, r, t, r0, c0);      gsync_grp(lsr, grp32);
        stage_fwe<1>(sm, ba, xtab, q, r, t, r0, c0);      gsync_grp(lsr, grp32);
        stage_ea(sm, be, badd, t, r0, c0);                gsync_grp(lsr, grp32);
    }
    for (int t = 0; t < Tlen; t++) {
        stage_lstm(sm, bih, bhh, t, r0, c0);              gsync_grp(lsr, grp32);
    }
    gsync(ls);                                            // head reads all rows
    stage_head(Wp, bp, out);
}

// ----------------------------------------------------------------------------
extern "C" void kernel_launch(void* const* d_in, const int* in_sizes, int n_in,
                              void* d_out, int out_size)
{
    const int*   q    = (const int*)d_in[0];
    const int*   r    = (const int*)d_in[1];
    const float* Mk   = (const float*)d_in[2];
    const float* Mv0  = (const float*)d_in[3];
    const float* ktab = (const float*)d_in[4];
    const float* xtab = (const float*)d_in[5];
    const float* We   = (const float*)d_in[6];
    const float* be   = (const float*)d_in[7];
    const float* Wadd = (const float*)d_in[8];
    const float* badd = (const float*)d_in[9];
    const float* Wa   = (const float*)d_in[10];
    const float* ba   = (const float*)d_in[11];
    const float* Wf   = (const float*)d_in[12];
    const float* bf   = (const float*)d_in[13];
    const float* Wih  = (const float*)d_in[14];
    const float* Whh  = (const float*)d_in[15];
    const float* bih  = (const float*)d_in[16];
    const float* bhh  = (const float*)d_in[17];
    const float* hx0  = (const float*)d_in[18];
    const float* cx0  = (const float*)d_in[19];
    const float* Wp   = (const float*)d_in[20];
    const float* bp   = (const float*)d_in[21];
    float* out = (float*)d_out;

    static bool attr_set = false;
    if (!attr_set) {
        cudaFuncSetAttribute(k_persist, cudaFuncAttributeMaxDynamicSharedMemorySize, SMEM_BYTES);
        attr_set = true;
    }
    k_persist<<<NBLK, NTHR, SMEM_BYTES>>>(q, r, Mk, Mv0, ktab, xtab, We, be, Wadd, badd,
                                          Wa, ba, Wf, bf, Wih, Whh, bih, bhh,
                                          hx0, cx0, Wp, bp, out);
}

// round 14
// speedup vs baseline: 1.4709x; 1.0758x over previous
#include <cuda_runtime.h>
#include <math.h>

#define Bsz 128
#define Tlen 48
#define Dm 512
#define NBLK 128
#define NTHR 512

// ---------------- global scratch ---------------------------------------------
__device__ float g_w[Bsz*Tlen*64];
__device__ unsigned long long g_code[Bsz*Tlen*2];
__device__ int g_src[Bsz*Tlen];
__device__ float g_read[Bsz*Dm];
__device__ float g_f[Bsz*Dm];
__device__ float g_we[Bsz*Dm];
__device__ float g_ft[Tlen*Bsz*Dm];
__device__ float g_H[(Tlen+1)*Bsz*Dm];
__device__ float g_C[(Tlen+1)*Bsz*Dm];
// k-major weight slabs (built once per launch by stage_wtr)
__device__ float g_WTf[16*1024*32];    // [cg][k][n]  Wf   (fp32)
__device__ float g_WTa2[16*1024*32];   // [cg][k][n]  Wa   (fp32)
__device__ float g_WTe[16*512*32];     // [cg][k][n]  We   (fp32)
__device__ float g_WTad[16*512*32];    // [cg][k][n]  Wadd (fp32)
__device__ float g_WTl[16*4*1024*32];  // [cg][gate][k(ih|hh)][n]  (tf32-rounded)
// barriers: monotonic counters (graph-replay safe)
__device__ unsigned g_count = 0;
__device__ volatile unsigned g_sense = 0;
__device__ unsigned g_gcnt[8*32];
__device__ volatile unsigned g_gsense[8*32];

__device__ __forceinline__ float sigm(float x) { return 1.0f / (1.0f + expf(-x)); }

// per-warp-group (128-thread) named barrier: ids 1..4
__device__ __forceinline__ void barg(int g) {
    asm volatile("bar.sync %0, 128;" :: "r"(g + 1) : "memory");
}

// tf32 round (rna) -> b32
__device__ __forceinline__ unsigned f2tf(float x) {
    unsigned u; asm("cvt.rna.tf32.f32 %0, %1;" : "=r"(u) : "f"(x)); return u;
}

// m16n8k8 tf32 mma, fp32 accumulate
__device__ __forceinline__ void mma_tf32(float (&d)[4], unsigned a0, unsigned a1,
                                         unsigned a2, unsigned a3,
                                         unsigned b0, unsigned b1) {
    asm volatile(
        "mma.sync.aligned.m16n8k8.row.col.f32.tf32.tf32.f32 "
        "{%0,%1,%2,%3}, {%4,%5,%6,%7}, {%8,%9}, {%0,%1,%2,%3};"
        : "+f"(d[0]), "+f"(d[1]), "+f"(d[2]), "+f"(d[3])
        : "r"(a0), "r"(a1), "r"(a2), "r"(a3), "r"(b0), "r"(b1));
}

// smem layout (floats):
// [0,32768) memS. During lstm phase this region is reused:
//   W buf0 [0,9216) = 4 gates x 2304, W buf1 [9216,18432), A tile [18432,19712)
// AS 4x640 | WS 4x1184 (W buf0 fwe/ea) | PART 16x576 (fwe/ea overlay W buf1 at g*2304) | wT | wN | i16
#define OFF_AS   32768
#define OFF_WS   35328
#define OFF_PART 40064
#define OFF_WT   49280
#define OFF_WN   50304
#define OFF_I16  51328
#define SMEM_FLOATS 51344
#define SMEM_BYTES (SMEM_FLOATS * 4)

// ---------------- cp.async helpers --------------------------------------------
__device__ __forceinline__ void cpa16(unsigned dst, const float* src) {
    asm volatile("cp.async.cg.shared.global [%0], [%1], 16;" :: "r"(dst), "l"(src));
}
__device__ __forceinline__ void cpa_commit() {
    asm volatile("cp.async.commit_group;" ::: "memory");
}
__device__ __forceinline__ void cpa_wait1() {
    asm volatile("cp.async.wait_group 1;" ::: "memory");
}
__device__ __forceinline__ void cpa_wait0() {
    asm volatile("cp.async.wait_group 0;" ::: "memory");
}

// ---------------- global grid barrier -----------------------------------------
__device__ __forceinline__ void gsync(unsigned& ls) {
    __syncthreads();
    if (threadIdx.x == 0) {
        unsigned target = ls + 1u;
        __threadfence();
        unsigned a = atomicAdd(&g_count, 1u) + 1u;
        if (a == target * (unsigned)NBLK) g_sense = target;
        while (g_sense != target) { }
        ls = target;
        __threadfence();
    }
    __syncthreads();
}

// ---------------- group barrier: 16 blocks sharing one row-group --------------
__device__ __forceinline__ void gsync_grp(unsigned& ls, int grp32) {
    __syncthreads();
    if (threadIdx.x == 0) {
        unsigned target = ls + 1u;
        __threadfence();
        unsigned a = atomicAdd(&g_gcnt[grp32], 1u) + 1u;
        if (a == target * 16u) g_gsense[grp32] = target;
        while (g_gsense[grp32] != target) { }
        ls = target;
        __threadfence();
    }
    __syncthreads();
}

__device__ __forceinline__ void fma16(float (&acc)[4][4], float4 a, float4 w) {
    acc[0][0]=fmaf(a.x,w.x,acc[0][0]); acc[0][1]=fmaf(a.x,w.y,acc[0][1]);
    acc[0][2]=fmaf(a.x,w.z,acc[0][2]); acc[0][3]=fmaf(a.x,w.w,acc[0][3]);
    acc[1][0]=fmaf(a.y,w.x,acc[1][0]); acc[1][1]=fmaf(a.y,w.y,acc[1][1]);
    acc[1][2]=fmaf(a.y,w.z,acc[1][2]); acc[1][3]=fmaf(a.y,w.w,acc[1][3]);
    acc[2][0]=fmaf(a.z,w.x,acc[2][0]); acc[2][1]=fmaf(a.z,w.y,acc[2][1]);
    acc[2][2]=fmaf(a.z,w.z,acc[2][2]); acc[2][3]=fmaf(a.z,w.w,acc[2][3]);
    acc[3][0]=fmaf(a.w,w.x,acc[3][0]); acc[3][1]=fmaf(a.w,w.y,acc[3][1]);
    acc[3][2]=fmaf(a.w,w.z,acc[3][2]); acc[3][3]=fmaf(a.w,w.w,acc[3][3]);
}

// ---------------- one-time k-major weight transposes --------------------------
__device__ void stage_wtr(const float* __restrict__ Wf, const float* __restrict__ Wa,
                          const float* __restrict__ We, const float* __restrict__ Wadd,
                          const float* __restrict__ Wih, const float* __restrict__ Whh)
{
    const int gid = blockIdx.x * NTHR + threadIdx.x;
    const int gs = NBLK * NTHR;   // 65536
    for (int d = gid; d < 16*1024*32; d += gs) {
        int cg = d >> 15, n = (d >> 10) & 31, k = d & 1023;
        int dst = (cg << 15) + k * 32 + n;
        g_WTf[dst]  = Wf[(size_t)(cg * 32 + n) * 1024 + k];
        g_WTa2[dst] = Wa[(size_t)(cg * 32 + n) * 1024 + k];
    }
    for (int d = gid; d < 16*512*32; d += gs) {
        int cg = d >> 14, n = (d >> 9) & 31, k = d & 511;
        int dst = (cg << 14) + k * 32 + n;
        g_WTe[dst]  = We[(size_t)(cg * 32 + n) * 512 + k];
        g_WTad[dst] = Wadd[(size_t)(cg * 32 + n) * 512 + k];
    }
    for (int d = gid; d < 16*4*1024*32; d += gs) {
        int cg = d >> 17, gate = (d >> 15) & 3, n = (d >> 10) & 31, k = d & 1023;
        int dst = ((cg * 4 + gate) << 15) + k * 32 + n;
        float v = (k < 512)
            ? Wih[(size_t)(gate * 512 + cg * 32 + n) * 512 + k]
            : Whh[(size_t)(gate * 512 + cg * 32 + n) * 512 + (k - 512)];
        g_WTl[dst] = __uint_as_float(f2tf(v));   // tf32-rounded for mma
    }
}

// ---------------- addressing GEMM: g_w[6144,64] = ktab[q] @ Mk^T -------------
__device__ void stage_addr(float* sm, const float* __restrict__ Mk,
                           const float* __restrict__ ktab, const int* __restrict__ q)
{
    float* As = sm + OFF_AS;      // [32][68]
    float* Ws = sm + OFF_WS;      // [32][36]
    float* part = sm + OFF_PART;  // [4][64][36]
    const int tid = threadIdx.x;
    const int s = tid >> 7, pos = tid & 127, rg = pos >> 3, cg = pos & 7;
    for (int tile = blockIdx.x; tile < 192; tile += NBLK) {
        const int row0 = (tile >> 1) * 64, cc0 = (tile & 1) * 32;
        float acc[4][4] = {};
#pragma unroll 1
        for (int ch = 0; ch < 16; ch++) {
            const int kb = ch * 32;
            {
                int rr = tid >> 3, kq = tid & 7;
                int qi = q[row0 + rr];
                float4 v = *(const float4*)(ktab + (size_t)qi * Dm + kb + kq * 4);
                float* a = As + (kq * 4) * 68 + rr;
                a[0] = v.x; a[68] = v.y; a[136] = v.z; a[204] = v.w;
            }
            if (tid < 256) {
                int n = tid >> 3, kq = tid & 7;
                float4 v = *(const float4*)(Mk + (size_t)(cc0 + n) * Dm + kb + kq * 4);
                float* w = Ws + (kq * 4) * 36 + n;
                w[0] = v.x; w[36] = v.y; w[72] = v.z; w[108] = v.w;
            }
            __syncthreads();
#pragma unroll
            for (int kk = 0; kk < 8; kk++) {
                int k = s * 8 + kk;
                float4 a4 = *(const float4*)(As + k * 68 + rg * 4);
                float4 w4 = *(const float4*)(Ws + k * 36 + cg * 4);
                fma16(acc, a4, w4);
            }
            __syncthreads();
        }
#pragma unroll
        for (int j = 0; j < 4; j++)
            *(float4*)(part + s * 2304 + (rg * 4 + j) * 36 + cg * 4) =
                make_float4(acc[j][0], acc[j][1], acc[j][2], acc[j][3]);
        __syncthreads();
        {
            int rr = tid >> 3, cgx = tid & 7;
            float4 v = make_float4(0.f, 0.f, 0.f, 0.f);
#pragma unroll
            for (int p = 0; p < 4; p++) {
                float4 u = *(const float4*)(part + p * 2304 + rr * 36 + cgx * 4);
                v.x += u.x; v.y += u.y; v.z += u.z; v.w += u.w;
            }
            *(float4*)(g_w + (size_t)(row0 + rr) * 64 + cc0 + cgx * 4) = v;
        }
        __syncthreads();
    }
}

// ---------------- softmax + triangular membership codes ----------------------
__device__ void stage_softmax(float* sm)
{
    unsigned char* ivb = (unsigned char*)(sm + OFF_WT);  // [16][64]
    const int wp = threadIdx.x >> 5, lane = threadIdx.x & 31;
    for (int rr = wp; rr < 48; rr += 16) {
        const int row = blockIdx.x * 48 + rr;
        float v0 = g_w[row * 64 + lane];
        float v1 = g_w[row * 64 + 32 + lane];
        float mx = fmaxf(v0, v1);
        for (int o = 16; o; o >>= 1) mx = fmaxf(mx, __shfl_xor_sync(0xffffffffu, mx, o));
        float e0 = expf(v0 - mx), e1 = expf(v1 - mx);
        float ss = e0 + e1;
        for (int o = 16; o; o >>= 1) ss += __shfl_xor_sync(0xffffffffu, ss, o);
        float inv = 1.0f / ss;
        float w0 = e0 * inv, w1 = e1 * inv;
        g_w[row * 64 + lane] = w0;
        g_w[row * 64 + 32 + lane] = w1;
        auto ivf = [](float w) -> int {
            float m = fmaxf(fminf((w - 0.075f) / (0.088f - 0.075f),
                                  (1.0f - w) / (1.0f - 0.088f)), 0.0f);
            return (m >= 0.6f) ? 2 : ((m >= 0.1f) ? 1 : 0);
        };
        ivb[wp * 64 + lane] = (unsigned char)ivf(w0);
        ivb[wp * 64 + 32 + lane] = (unsigned char)ivf(w1);
        __syncwarp();
        if (lane == 0) {
            unsigned long long c0 = 0ull, c1 = 0ull;
            for (int i = 0; i < 32; i++) {
                c0 |= (unsigned long long)ivb[wp * 64 + i] << (2 * i);
                c1 |= (unsigned long long)ivb[wp * 64 + 32 + i] << (2 * i);
            }
            g_code[row * 2] = c0;
            g_code[row * 2 + 1] = c1;
        }
        __syncwarp();
    }
}

// ---------------- src scan + memS / H0 / C0 / read_0 init --------------------
__device__ void stage_init(float* sm, const float* __restrict__ Mv0,
                           const float* __restrict__ hx0, const float* __restrict__ cx0,
                           int r0, int c0)
{
    float* memS = sm;
    float* wT = sm + OFF_WT;
    const int tid = threadIdx.x;
    if (tid < Tlen) {
        const int b = blockIdx.x, i = tid;
        unsigned long long cc0 = g_code[(b * Tlen + i) * 2];
        unsigned long long cc1 = g_code[(b * Tlen + i) * 2 + 1];
        int sv = i - 1;
        for (int j = i - 1; j >= 0; j--)
            if (g_code[(b * Tlen + j) * 2] == cc0 && g_code[(b * Tlen + j) * 2 + 1] == cc1) { sv = j; break; }
        g_src[b * Tlen + i] = sv;
    }
    for (int i = tid; i < 32768; i += NTHR) {
        int m = (i >> 5) & 63, cc = i & 31;
        memS[i] = Mv0[m * Dm + c0 + cc];
    }
    for (int i = tid; i < 1024; i += NTHR) {
        int bl = i >> 6, m = i & 63;
        wT[i] = g_w[((r0 + bl) * Tlen) * 64 + m];
    }
    __syncthreads();
    const int rr = tid >> 5, cc = tid & 31;
    const int b = r0 + rr, col = c0 + cc;
    g_H[(size_t)b * Dm + col] = hx0[col];
    g_C[(size_t)b * Dm + col] = cx0[col];
    float racc = 0.f;
#pragma unroll 4
    for (int m = 0; m < 64; m++)
        racc = fmaf(wT[rr * 64 + m], memS[(rr * 64 + m) * 32 + cc], racc);
    g_read[(size_t)b * Dm + col] = racc;
}

// ---------------- f / we GEMM (pipelined, k-major W slab, LDS.128 W) ---------
template<int MODE>   // 0: f = tanh(.), X=g_read, tab=ktab ; 1: we = raw, X=g_f, tab=xtab
__device__ void stage_fwe(float* sm, const float* __restrict__ bias,
                          const float* __restrict__ tab, const int* __restrict__ q,
                          const int* __restrict__ r, int t, int r0, int c0)
{
    float* As = sm + OFF_AS;
    float* part = sm + OFF_PART;
    int* sQ = (int*)(sm + OFF_I16);
    const int tid = threadIdx.x;
    const int g = tid >> 7, gt = tid & 127;
    const int s = gt >> 5, pos = gt & 31, rg = pos >> 3, cg = pos & 7;
    if (tid < 16) {
        int b = r0 + tid;
        int qi = q[b * Tlen + t];
        sQ[tid] = (MODE == 0) ? qi : (qi + 2000 * r[b * Tlen + t]);
    }
    __syncthreads();
    const float* X = (MODE == 0) ? g_read : g_f;
    const float* slab = ((MODE == 0) ? g_WTf : g_WTa2) + ((size_t)(c0 >> 5) << 15);

    const int wk0 = (gt * 2) >> 3, wsg0 = (gt * 2) & 7;
    const int wk1 = (gt * 2 + 1) >> 3, wsg1 = (gt * 2 + 1) & 7;
    float* wb0p = sm + OFF_WS + g * 1184;
    float* wb1p = part + g * 2304;
    unsigned wbu0 = (unsigned)__cvta_generic_to_shared(wb0p);
    unsigned wbu1 = (unsigned)__cvta_generic_to_shared(wb1p);
    const unsigned wo0 = (unsigned)(wk0 * 36 + wsg0 * 4) * 4u;
    const unsigned wo1 = (unsigned)(wk1 * 36 + wsg1 * 4) * 4u;
    const int arr = gt >> 3, akq = gt & 7;

    {
        int kb = g * 256;
        cpa16(wbu0 + wo0, slab + (size_t)(kb + wk0) * 32 + wsg0 * 4);
        cpa16(wbu0 + wo1, slab + (size_t)(kb + wk1) * 32 + wsg1 * 4);
        cpa_commit();
    }
    float4 aR;
    {
        int kb = g * 256;
        const float* srcp = (g < 2) ? X + (size_t)(r0 + arr) * Dm + kb + akq * 4
                                    : tab + (size_t)sQ[arr] * Dm + (kb - Dm) + akq * 4;
        aR = *(const float4*)srcp;
    }
    float acc[4][4] = {};
#pragma unroll 1
    for (int ch = 0; ch < 8; ch++) {
        if (ch < 7) {
            int kb = g * 256 + (ch + 1) * 32;
            unsigned wd = ((ch + 1) & 1) ? wbu1 : wbu0;
            cpa16(wd + wo0, slab + (size_t)(kb + wk0) * 32 + wsg0 * 4);
            cpa16(wd + wo1, slab + (size_t)(kb + wk1) * 32 + wsg1 * 4);
            cpa_commit();
        }
        {
            float* a = As + g * 640 + (akq * 4) * 20 + arr;
            a[0] = aR.x; a[20] = aR.y; a[40] = aR.z; a[60] = aR.w;
        }
        float4 aN = aR;
        if (ch < 7) {
            int kb = g * 256 + (ch + 1) * 32;
            const float* srcp = (g < 2) ? X + (size_t)(r0 + arr) * Dm + kb + akq * 4
                                        : tab + (size_t)sQ[arr] * Dm + (kb - Dm) + akq * 4;
            aN = *(const float4*)srcp;
            cpa_wait1();
        } else {
            cpa_wait0();
        }
        barg(g);
        const float* Wb = (ch & 1) ? wb1p : wb0p;
#pragma unroll
        for (int kk = 0; kk < 8; kk++) {
            int k = s * 8 + kk;
            float4 a4 = *(const float4*)(As + g * 640 + k * 20 + rg * 4);
            float4 w4 = *(const float4*)(Wb + k * 36 + cg * 4);
            fma16(acc, a4, w4);
        }
        aR = aN;
        barg(g);
    }
    const int sid = g * 4 + s;
#pragma unroll
    for (int j = 0; j < 4; j++)
        *(float4*)(part + sid * 576 + (rg * 4 + j) * 36 + cg * 4) =
            make_float4(acc[j][0], acc[j][1], acc[j][2], acc[j][3]);
    __syncthreads();
    {
        const int rr = tid >> 5, cc = tid & 31;
        float v = 0.f;
#pragma unroll
        for (int p = 0; p < 16; p++) v += part[p * 576 + rr * 36 + cc];
        v += bias[c0 + cc];
        const int b = r0 + rr;
        if (MODE == 0) {
            v = tanhf(v);
            g_f[(size_t)b * Dm + c0 + cc] = v;
            g_ft[((size_t)t * Bsz + b) * Dm + c0 + cc] = v;
        } else {
            g_we[(size_t)b * Dm + c0 + cc] = v;
        }
    }
}

// ---------------- e/a GEMMs + smem memory update (pipelined, slab W) ---------
__device__ void stage_ea(float* sm, const float* __restrict__ be,
                         const float* __restrict__ ba, int t, int r0, int c0)
{
    float* memS = sm;
    float* As = sm + OFF_AS;
    float* part = sm + OFF_PART;
    float* wT = sm + OFF_WT;
    float* wN = sm + OFF_WN;
    const int tid = threadIdx.x;
    const int g = tid >> 7, gt = tid & 127;
    const int s = gt >> 5, pos = gt & 31, rg = pos >> 3, cg = pos & 7;
    for (int i = tid; i < 1024; i += NTHR) {
        int bl = i >> 6, m = i & 63;
        wT[i] = g_w[((r0 + bl) * Tlen + t) * 64 + m];
        wN[i] = (t + 1 < Tlen) ? g_w[((r0 + bl) * Tlen + t + 1) * 64 + m] : 0.0f;
    }
    __syncthreads();
    const float* slab = ((g < 2) ? g_WTe : g_WTad) + ((size_t)(c0 >> 5) << 14);

    const int wk0 = (gt * 2) >> 3, wsg0 = (gt * 2) & 7;
    const int wk1 = (gt * 2 + 1) >> 3, wsg1 = (gt * 2 + 1) & 7;
    float* wb0p = sm + OFF_WS + g * 1184;
    float* wb1p = part + g * 2304;
    unsigned wbu0 = (unsigned)__cvta_generic_to_shared(wb0p);
    unsigned wbu1 = (unsigned)__cvta_generic_to_shared(wb1p);
    const unsigned wo0 = (unsigned)(wk0 * 36 + wsg0 * 4) * 4u;
    const unsigned wo1 = (unsigned)(wk1 * 36 + wsg1 * 4) * 4u;
    const int arr = gt >> 3, akq = gt & 7;
    const int kh = (g & 1) * 256;

    {
        cpa16(wbu0 + wo0, slab + (size_t)(kh + wk0) * 32 + wsg0 * 4);
        cpa16(wbu0 + wo1, slab + (size_t)(kh + wk1) * 32 + wsg1 * 4);
        cpa_commit();
    }
    float4 aR = *(const float4*)(g_we + (size_t)(r0 + arr) * Dm + kh + akq * 4);
    float acc[4][4] = {};
#pragma unroll 1
    for (int ch = 0; ch < 8; ch++) {
        if (ch < 7) {
            int kb = kh + (ch + 1) * 32;
            unsigned wd = ((ch + 1) & 1) ? wbu1 : wbu0;
            cpa16(wd + wo0, slab + (size_t)(kb + wk0) * 32 + wsg0 * 4);
            cpa16(wd + wo1, slab + (size_t)(kb + wk1) * 32 + wsg1 * 4);
            cpa_commit();
        }
        {
            float* a = As + g * 640 + (akq * 4) * 20 + arr;
            a[0] = aR.x; a[20] = aR.y; a[40] = aR.z; a[60] = aR.w;
        }
        float4 aN = aR;
        if (ch < 7) {
            int kb = kh + (ch + 1) * 32;
            aN = *(const float4*)(g_we + (size_t)(r0 + arr) * Dm + kb + akq * 4);
            cpa_wait1();
        } else {
            cpa_wait0();
        }
        barg(g);
        const float* Wb = (ch & 1) ? wb1p : wb0p;
#pragma unroll
        for (int kk = 0; kk < 8; kk++) {
            int k = s * 8 + kk;
            float4 a4 = *(const float4*)(As + g * 640 + k * 20 + rg * 4);
            float4 w4 = *(const float4*)(Wb + k * 36 + cg * 4);
            fma16(acc, a4, w4);
        }
        aR = aN;
        barg(g);
    }
    const int sid = g * 4 + s;
#pragma unroll
    for (int j = 0; j < 4; j++)
        *(float4*)(part + sid * 576 + (rg * 4 + j) * 36 + cg * 4) =
            make_float4(acc[j][0], acc[j][1], acc[j][2], acc[j][3]);
    __syncthreads();
    {
        const int rr = tid >> 5, cc = tid & 31;
        float ve = 0.f, va = 0.f;
#pragma unroll
        for (int p = 0; p < 8; p++)  ve += part[p * 576 + rr * 36 + cc];
#pragma unroll
        for (int p = 8; p < 16; p++) va += part[p * 576 + rr * 36 + cc];
        ve = sigm(ve + be[c0 + cc]);
        va = tanhf(va + ba[c0 + cc]);
        float racc = 0.f;
#pragma unroll 4
        for (int m = 0; m < 64; m++) {
            float wt = wT[rr * 64 + m], wn = wN[rr * 64 + m];
            float* p = &memS[(rr * 64 + m) * 32 + cc];
            float v = *p;
            v = v * (1.0f - wt * ve) + wt * va;
            *p = v;
            racc = fmaf(wn, v, racc);
        }
        g_read[(size_t)(r0 + rr) * Dm + c0 + cc] = racc;
    }
}

// ---------------- hop-LSTM step: tf32 mma.sync, 16 x 64-k chunks --------------
// warps: w = tid>>5; gate = w>>2; k-slice s = w&3 (k in [s*16,(s+1)*16) per chunk)
__device__ void stage_lstm(float* sm, const float* __restrict__ bih,
                           const float* __restrict__ bhh, int t, int r0, int c0)
{
    float* part = sm + OFF_PART;
    int* s16 = (int*)(sm + OFF_I16);
    const int tid = threadIdx.x;
    const int w = tid >> 5, lane = tid & 31;
    const int gate = w >> 2, ks = w & 3;
    const int g = tid >> 7, gt = tid & 127;   // staging role (gate g's W buffer)
    if (tid < 16) s16[tid] = g_src[(r0 + tid) * Tlen + t] + 1;
    __syncthreads();

    const float* slab = g_WTl + ((size_t)((c0 >> 5) * 4 + g) << 15);
    // W staging: 4 cp.async per thread into gate-g buffer [64][36]
    int wk[4], wsg[4]; unsigned wo[4];
#pragma unroll
    for (int h = 0; h < 4; h++) {
        int i = gt * 4 + h;
        wk[h] = i >> 3; wsg[h] = i & 7;
        wo[h] = (unsigned)(wk[h] * 36 + wsg[h] * 4) * 4u;
    }
    float* wbB0 = sm + g * 2304;           // buf0: [0,9216)
    float* wbB1 = sm + 9216 + g * 2304;    // buf1: [9216,18432)
    unsigned wbu0 = (unsigned)__cvta_generic_to_shared(wbB0);
    unsigned wbu1 = (unsigned)__cvta_generic_to_shared(wbB1);
    float* aLp = sm + 18432;               // shared A tile [64][20]
    unsigned* aLu = (unsigned*)aLp;

    // A staging: tid<256, row = tid&15, seg = tid>>4 (k-local = seg*4)
    const int arow = tid & 15, aseg = tid >> 4;
    const float* aF = g_ft + ((size_t)t * Bsz + r0 + arow) * Dm + aseg * 4;
    const float* aH = g_H + ((size_t)s16[arow] * Bsz + r0 + arow) * Dm + aseg * 4;

    {   // chunk 0 issues
#pragma unroll
        for (int h = 0; h < 4; h++)
            cpa16(wbu0 + wo[h], slab + (size_t)wk[h] * 32 + wsg[h] * 4);
        cpa_commit();
    }
    float4 aR = make_float4(0.f, 0.f, 0.f, 0.f);
    if (tid < 256) aR = *(const float4*)aF;

    float dacc[4][4] = {};   // [ntile][frag]
#pragma unroll 1
    for (int ch = 0; ch < 16; ch++) {
        if (ch < 15) {
            int kb = (ch + 1) * 64;
            unsigned wd = ((ch + 1) & 1) ? wbu1 : wbu0;
#pragma unroll
            for (int h = 0; h < 4; h++)
                cpa16(wd + wo[h], slab + (size_t)(kb + wk[h]) * 32 + wsg[h] * 4);
            cpa_commit();
        }
        if (tid < 256) {   // store A chunk ch (k-major, tf32-rounded)
            unsigned* a = aLu + (aseg * 4) * 20 + arow;
            a[0]  = f2tf(aR.x); a[20] = f2tf(aR.y);
            a[40] = f2tf(aR.z); a[60] = f2tf(aR.w);
        }
        float4 aN = aR;
        if (ch < 15) {
            int kb = (ch + 1) * 64;   // chunks 0-7 -> ft, 8-15 -> H
            if (tid < 256) {
                const float* basep = (kb < Dm) ? aF + kb : aH + (kb - Dm);
                aN = *(const float4*)basep;
            }
            cpa_wait1();
        } else {
            cpa_wait0();
        }
        __syncthreads();
        const unsigned* Wb = (const unsigned*)(((ch & 1) ? wbB1 : wbB0)) ;
        // note: Wb here is this thread's COMPUTE gate buffer:
        const unsigned* Wg = (const unsigned*)(((ch & 1) ? (sm + 9216) : sm)) + gate * 2304;
        (void)Wb;
#pragma unroll
        for (int kt = 0; kt < 2; kt++) {
            const int kl = ks * 16 + kt * 8;
            unsigned a0 = aLu[(kl + (lane & 3)) * 20 + (lane >> 2)];
            unsigned a1 = aLu[(kl + (lane & 3)) * 20 + (lane >> 2) + 8];
            unsigned a2 = aLu[(kl + 4 + (lane & 3)) * 20 + (lane >> 2)];
            unsigned a3 = aLu[(kl + 4 + (lane & 3)) * 20 + (lane >> 2) + 8];
#pragma unroll
            for (int nt = 0; nt < 4; nt++) {
                unsigned b0 = Wg[(kl + (lane & 3)) * 36 + nt * 8 + (lane >> 2)];
                unsigned b1 = Wg[(kl + 4 + (lane & 3)) * 36 + nt * 8 + (lane >> 2)];
                mma_tf32(dacc[nt], a0, a1, a2, a3, b0, b1);
            }
        }
        aR = aN;
        __syncthreads();
    }
    // fragment epilogue -> part slots (sid = gate*4 + ks), then standard reduce
    const int sid = gate * 4 + ks;
    {
        const int row = lane >> 2, colb = (lane & 3) * 2;
#pragma unroll
        for (int nt = 0; nt < 4; nt++) {
            float* pb = part + sid * 576;
            pb[row * 36 + nt * 8 + colb]           = dacc[nt][0];
            pb[row * 36 + nt * 8 + colb + 1]       = dacc[nt][1];
            pb[(row + 8) * 36 + nt * 8 + colb]     = dacc[nt][2];
            pb[(row + 8) * 36 + nt * 8 + colb + 1] = dacc[nt][3];
        }
    }
    __syncthreads();
    {
        const int rr = tid >> 5, cc = tid & 31;
        float gi = 0.f, gf = 0.f, gg = 0.f, go = 0.f;
#pragma unroll
        for (int p = 0; p < 4; p++)   gi += part[p * 576 + rr * 36 + cc];
#pragma unroll
        for (int p = 4; p < 8; p++)   gf += part[p * 576 + rr * 36 + cc];
#pragma unroll
        for (int p = 8; p < 12; p++)  gg += part[p * 576 + rr * 36 + cc];
#pragma unroll
        for (int p = 12; p < 16; p++) go += part[p * 576 + rr * 36 + cc];
        const int b = r0 + rr, col = c0 + cc;
        gi += bih[col] + bhh[col];
        gf += bih[512 + col] + bhh[512 + col];
        gg += bih[1024 + col] + bhh[1024 + col];
        go += bih[1536 + col] + bhh[1536 + col];
        float cin = g_C[((size_t)s16[rr] * Bsz + b) * Dm + col];
        float cn = sigm(gf) * cin + sigm(gi) * tanhf(gg);
        float hn = sigm(go) * tanhf(cn);
        g_C[((size_t)(t + 1) * Bsz + b) * Dm + col] = cn;
        g_H[((size_t)(t + 1) * Bsz + b) * Dm + col] = hn;
    }
}

// ---------------- prediction head --------------------------------------------
__device__ void stage_head(const float* __restrict__ Wp, const float* __restrict__ bp,
                           float* __restrict__ out)
{
    const int wp = threadIdx.x >> 5, lane = threadIdx.x & 31;
    for (int bt = blockIdx.x * 16 + wp; bt < Bsz * Tlen; bt += NBLK * 16) {
        const int b = bt / Tlen, t = bt % Tlen;
        const float* h = &g_H[((size_t)(t + 1) * Bsz + b) * Dm];
        float s = 0.f;
        for (int i = lane; i < Dm; i += 32) s = fmaf(h[i], Wp[i], s);
        for (int o = 16; o; o >>= 1) s += __shfl_xor_sync(0xffffffffu, s, o);
        if (lane == 0) out[bt] = sigm(s + bp[0]);
    }
}

// ---------------- the single persistent kernel -------------------------------
__global__ void __launch_bounds__(NTHR, 1) k_persist(
    const int* __restrict__ q, const int* __restrict__ r,
    const float* __restrict__ Mk, const float* __restrict__ Mv0,
    const float* __restrict__ ktab, const float* __restrict__ xtab,
    const float* __restrict__ We, const float* __restrict__ be,
    const float* __restrict__ Wadd, const float* __restrict__ badd,
    const float* __restrict__ Wa, const float* __restrict__ ba,
    const float* __restrict__ Wf, const float* __restrict__ bf,
    const float* __restrict__ Wih, const float* __restrict__ Whh,
    const float* __restrict__ bih, const float* __restrict__ bhh,
    const float* __restrict__ hx0, const float* __restrict__ cx0,
    const float* __restrict__ Wp, const float* __restrict__ bp,
    float* __restrict__ out)
{
    extern __shared__ float sm[];
    const int grp = blockIdx.x & 7;
    const int grp32 = grp * 32;
    unsigned ls = 0, lsr = 0;
    if (threadIdx.x == 0) { ls = g_sense; lsr = g_gsense[grp32]; }
    const int r0 = grp * 16;
    const int c0 = (blockIdx.x >> 3) * 32;

    stage_wtr(Wf, Wa, We, Wadd, Wih, Whh);
    stage_addr(sm, Mk, ktab, q);                          gsync(ls);
    stage_softmax(sm);                                    gsync(ls);
    stage_init(sm, Mv0, hx0, cx0, r0, c0);                gsync(ls);

    for (int t = 0; t < Tlen; t++) {
        stage_fwe<0>(sm, bf, ktab, q, r, t, r0, c0);      gsync_grp(lsr, grp32);
        stage_fwe<1>(sm, ba, xtab, q, r, t, r0, c0);      gsync_grp(lsr, grp32);
        stage_ea(sm, be, badd, t, r0, c0);                gsync_grp(lsr, grp32);
    }
    for (int t = 0; t < Tlen; t++) {
        stage_lstm(sm, bih, bhh, t, r0, c0);              gsync_grp(lsr, grp32);
    }
    gsync(ls);                                            // head reads all rows
    stage_head(Wp, bp, out);
}

// ----------------------------------------------------------------------------
extern "C" void kernel_launch(void* const* d_in, const int* in_sizes, int n_in,
                              void* d_out, int out_size)
{
    const int*   q    = (const int*)d_in[0];
    const int*   r    = (const int*)d_in[1];
    const float* Mk   = (const float*)d_in[2];
    const float* Mv0  = (const float*)d_in[3];
    const float* ktab = (const float*)d_in[4];
    const float* xtab = (const float*)d_in[5];
    const float* We   = (const float*)d_in[6];
    const float* be   = (const float*)d_in[7];
    const float* Wadd = (const float*)d_in[8];
    const float* badd = (const float*)d_in[9];
    const float* Wa   = (const float*)d_in[10];
    const float* ba   = (const float*)d_in[11];
    const float* Wf   = (const float*)d_in[12];
    const float* bf   = (const float*)d_in[13];
    const float* Wih  = (const float*)d_in[14];
    const float* Whh  = (const float*)d_in[15];
    const float* bih  = (const float*)d_in[16];
    const float* bhh  = (const float*)d_in[17];
    const float* hx0  = (const float*)d_in[18];
    const float* cx0  = (const float*)d_in[19];
    const float* Wp   = (const float*)d_in[20];
    const float* bp   = (const float*)d_in[21];
    float* out = (float*)d_out;

    static bool attr_set = false;
    if (!attr_set) {
        cudaFuncSetAttribute(k_persist, cudaFuncAttributeMaxDynamicSharedMemorySize, SMEM_BYTES);
        attr_set = true;
    }
    k_persist<<<NBLK, NTHR, SMEM_BYTES>>>(q, r, Mk, Mv0, ktab, xtab, We, be, Wadd, badd,
                                          Wa, ba, Wf, bf, Wih, Whh, bih, bhh,
                                          hx0, cx0, Wp, bp, out);
}

// round 15
// speedup vs baseline: 1.5772x; 1.0723x over previous
#include <cuda_runtime.h>
#include <math.h>

#define Bsz 128
#define Tlen 48
#define Dm 512
#define NBLK 128
#define NTHR 512

// ---------------- global scratch ---------------------------------------------
__device__ float g_w[Bsz*Tlen*64];
__device__ unsigned long long g_code[Bsz*Tlen*2];
__device__ int g_src[Bsz*Tlen];
__device__ float g_read[Bsz*Dm];
__device__ float g_f[Bsz*Dm];
__device__ float g_we[Bsz*Dm];
__device__ float g_ft[Tlen*Bsz*Dm];
__device__ float g_H[(Tlen+1)*Bsz*Dm];
__device__ float g_C[(Tlen+1)*Bsz*Dm];
// k-major weight slabs (built once per launch by stage_wtr; tf32-rounded for mma)
__device__ float g_WTf[16*1024*32];    // [cg][k][n]  Wf   (tf32)
__device__ float g_WTa2[16*1024*32];   // [cg][k][n]  Wa   (tf32)
__device__ float g_WTe[16*512*32];     // [cg][k][n]  We   (tf32)
__device__ float g_WTad[16*512*32];    // [cg][k][n]  Wadd (tf32)
__device__ float g_WTl[16*4*1024*32];  // [cg][gate][k(ih|hh)][n]  (tf32)
// barriers: monotonic counters (graph-replay safe)
__device__ unsigned g_count = 0;
__device__ volatile unsigned g_sense = 0;
__device__ unsigned g_gcnt[8*32];
__device__ volatile unsigned g_gsense[8*32];

__device__ __forceinline__ float sigm(float x) { return 1.0f / (1.0f + expf(-x)); }

// per-warp-group (128-thread) named barrier: ids 1..4
__device__ __forceinline__ void barg(int g) {
    asm volatile("bar.sync %0, 128;" :: "r"(g + 1) : "memory");
}

// tf32 round (rna) -> b32
__device__ __forceinline__ unsigned f2tf(float x) {
    unsigned u; asm("cvt.rna.tf32.f32 %0, %1;" : "=r"(u) : "f"(x)); return u;
}

// m16n8k8 tf32 mma, fp32 accumulate
__device__ __forceinline__ void mma_tf32(float (&d)[4], unsigned a0, unsigned a1,
                                         unsigned a2, unsigned a3,
                                         unsigned b0, unsigned b1) {
    asm volatile(
        "mma.sync.aligned.m16n8k8.row.col.f32.tf32.tf32.f32 "
        "{%0,%1,%2,%3}, {%4,%5,%6,%7}, {%8,%9}, {%0,%1,%2,%3};"
        : "+f"(d[0]), "+f"(d[1]), "+f"(d[2]), "+f"(d[3])
        : "r"(a0), "r"(a1), "r"(a2), "r"(a3), "r"(b0), "r"(b1));
}

// smem layout (floats):
// [0,32768) memS. During lstm phase reused: W buf0 [0,9216), buf1 [9216,18432), A [18432,19712)
// AS 4x640 | WS 4x1184 (W buf0 fwe/ea) | PART 16x576 (fwe/ea overlay W buf1 at g*2304) | wT | wN | i16
#define OFF_AS   32768
#define OFF_WS   35328
#define OFF_PART 40064
#define OFF_WT   49280
#define OFF_WN   50304
#define OFF_I16  51328
#define SMEM_FLOATS 51344
#define SMEM_BYTES (SMEM_FLOATS * 4)

// ---------------- cp.async helpers --------------------------------------------
__device__ __forceinline__ void cpa16(unsigned dst, const float* src) {
    asm volatile("cp.async.cg.shared.global [%0], [%1], 16;" :: "r"(dst), "l"(src));
}
__device__ __forceinline__ void cpa_commit() {
    asm volatile("cp.async.commit_group;" ::: "memory");
}
__device__ __forceinline__ void cpa_wait1() {
    asm volatile("cp.async.wait_group 1;" ::: "memory");
}
__device__ __forceinline__ void cpa_wait0() {
    asm volatile("cp.async.wait_group 0;" ::: "memory");
}

// ---------------- global grid barrier -----------------------------------------
__device__ __forceinline__ void gsync(unsigned& ls) {
    __syncthreads();
    if (threadIdx.x == 0) {
        unsigned target = ls + 1u;
        __threadfence();
        unsigned a = atomicAdd(&g_count, 1u) + 1u;
        if (a == target * (unsigned)NBLK) g_sense = target;
        while (g_sense != target) { }
        ls = target;
        __threadfence();
    }
    __syncthreads();
}

// ---------------- group barrier: 16 blocks sharing one row-group --------------
__device__ __forceinline__ void gsync_grp(unsigned& ls, int grp32) {
    __syncthreads();
    if (threadIdx.x == 0) {
        unsigned target = ls + 1u;
        __threadfence();
        unsigned a = atomicAdd(&g_gcnt[grp32], 1u) + 1u;
        if (a == target * 16u) g_gsense[grp32] = target;
        while (g_gsense[grp32] != target) { }
        ls = target;
        __threadfence();
    }
    __syncthreads();
}

__device__ __forceinline__ void fma16(float (&acc)[4][4], float4 a, float4 w) {
    acc[0][0]=fmaf(a.x,w.x,acc[0][0]); acc[0][1]=fmaf(a.x,w.y,acc[0][1]);
    acc[0][2]=fmaf(a.x,w.z,acc[0][2]); acc[0][3]=fmaf(a.x,w.w,acc[0][3]);
    acc[1][0]=fmaf(a.y,w.x,acc[1][0]); acc[1][1]=fmaf(a.y,w.y,acc[1][1]);
    acc[1][2]=fmaf(a.y,w.z,acc[1][2]); acc[1][3]=fmaf(a.y,w.w,acc[1][3]);
    acc[2][0]=fmaf(a.z,w.x,acc[2][0]); acc[2][1]=fmaf(a.z,w.y,acc[2][1]);
    acc[2][2]=fmaf(a.z,w.z,acc[2][2]); acc[2][3]=fmaf(a.z,w.w,acc[2][3]);
    acc[3][0]=fmaf(a.w,w.x,acc[3][0]); acc[3][1]=fmaf(a.w,w.y,acc[3][1]);
    acc[3][2]=fmaf(a.w,w.z,acc[3][2]); acc[3][3]=fmaf(a.w,w.w,acc[3][3]);
}

// ---------------- one-time k-major weight transposes (tf32-rounded) -----------
__device__ void stage_wtr(const float* __restrict__ Wf, const float* __restrict__ Wa,
                          const float* __restrict__ We, const float* __restrict__ Wadd,
                          const float* __restrict__ Wih, const float* __restrict__ Whh)
{
    const int gid = blockIdx.x * NTHR + threadIdx.x;
    const int gs = NBLK * NTHR;   // 65536
    for (int d = gid; d < 16*1024*32; d += gs) {
        int cg = d >> 15, n = (d >> 10) & 31, k = d & 1023;
        int dst = (cg << 15) + k * 32 + n;
        g_WTf[dst]  = __uint_as_float(f2tf(Wf[(size_t)(cg * 32 + n) * 1024 + k]));
        g_WTa2[dst] = __uint_as_float(f2tf(Wa[(size_t)(cg * 32 + n) * 1024 + k]));
    }
    for (int d = gid; d < 16*512*32; d += gs) {
        int cg = d >> 14, n = (d >> 9) & 31, k = d & 511;
        int dst = (cg << 14) + k * 32 + n;
        g_WTe[dst]  = __uint_as_float(f2tf(We[(size_t)(cg * 32 + n) * 512 + k]));
        g_WTad[dst] = __uint_as_float(f2tf(Wadd[(size_t)(cg * 32 + n) * 512 + k]));
    }
    for (int d = gid; d < 16*4*1024*32; d += gs) {
        int cg = d >> 17, gate = (d >> 15) & 3, n = (d >> 10) & 31, k = d & 1023;
        int dst = ((cg * 4 + gate) << 15) + k * 32 + n;
        float v = (k < 512)
            ? Wih[(size_t)(gate * 512 + cg * 32 + n) * 512 + k]
            : Whh[(size_t)(gate * 512 + cg * 32 + n) * 512 + (k - 512)];
        g_WTl[dst] = __uint_as_float(f2tf(v));
    }
}

// ---------------- addressing GEMM: g_w[6144,64] = ktab[q] @ Mk^T (fp32) ------
__device__ void stage_addr(float* sm, const float* __restrict__ Mk,
                           const float* __restrict__ ktab, const int* __restrict__ q)
{
    float* As = sm + OFF_AS;      // [32][68]
    float* Ws = sm + OFF_WS;      // [32][36]
    float* part = sm + OFF_PART;  // [4][64][36]
    const int tid = threadIdx.x;
    const int s = tid >> 7, pos = tid & 127, rg = pos >> 3, cg = pos & 7;
    for (int tile = blockIdx.x; tile < 192; tile += NBLK) {
        const int row0 = (tile >> 1) * 64, cc0 = (tile & 1) * 32;
        float acc[4][4] = {};
#pragma unroll 1
        for (int ch = 0; ch < 16; ch++) {
            const int kb = ch * 32;
            {
                int rr = tid >> 3, kq = tid & 7;
                int qi = q[row0 + rr];
                float4 v = *(const float4*)(ktab + (size_t)qi * Dm + kb + kq * 4);
                float* a = As + (kq * 4) * 68 + rr;
                a[0] = v.x; a[68] = v.y; a[136] = v.z; a[204] = v.w;
            }
            if (tid < 256) {
                int n = tid >> 3, kq = tid & 7;
                float4 v = *(const float4*)(Mk + (size_t)(cc0 + n) * Dm + kb + kq * 4);
                float* w = Ws + (kq * 4) * 36 + n;
                w[0] = v.x; w[36] = v.y; w[72] = v.z; w[108] = v.w;
            }
            __syncthreads();
#pragma unroll
            for (int kk = 0; kk < 8; kk++) {
                int k = s * 8 + kk;
                float4 a4 = *(const float4*)(As + k * 68 + rg * 4);
                float4 w4 = *(const float4*)(Ws + k * 36 + cg * 4);
                fma16(acc, a4, w4);
            }
            __syncthreads();
        }
#pragma unroll
        for (int j = 0; j < 4; j++)
            *(float4*)(part + s * 2304 + (rg * 4 + j) * 36 + cg * 4) =
                make_float4(acc[j][0], acc[j][1], acc[j][2], acc[j][3]);
        __syncthreads();
        {
            int rr = tid >> 3, cgx = tid & 7;
            float4 v = make_float4(0.f, 0.f, 0.f, 0.f);
#pragma unroll
            for (int p = 0; p < 4; p++) {
                float4 u = *(const float4*)(part + p * 2304 + rr * 36 + cgx * 4);
                v.x += u.x; v.y += u.y; v.z += u.z; v.w += u.w;
            }
            *(float4*)(g_w + (size_t)(row0 + rr) * 64 + cc0 + cgx * 4) = v;
        }
        __syncthreads();
    }
}

// ---------------- softmax + triangular membership codes ----------------------
__device__ void stage_softmax(float* sm)
{
    unsigned char* ivb = (unsigned char*)(sm + OFF_WT);  // [16][64]
    const int wp = threadIdx.x >> 5, lane = threadIdx.x & 31;
    for (int rr = wp; rr < 48; rr += 16) {
        const int row = blockIdx.x * 48 + rr;
        float v0 = g_w[row * 64 + lane];
        float v1 = g_w[row * 64 + 32 + lane];
        float mx = fmaxf(v0, v1);
        for (int o = 16; o; o >>= 1) mx = fmaxf(mx, __shfl_xor_sync(0xffffffffu, mx, o));
        float e0 = expf(v0 - mx), e1 = expf(v1 - mx);
        float ss = e0 + e1;
        for (int o = 16; o; o >>= 1) ss += __shfl_xor_sync(0xffffffffu, ss, o);
        float inv = 1.0f / ss;
        float w0 = e0 * inv, w1 = e1 * inv;
        g_w[row * 64 + lane] = w0;
        g_w[row * 64 + 32 + lane] = w1;
        auto ivf = [](float w) -> int {
            float m = fmaxf(fminf((w - 0.075f) / (0.088f - 0.075f),
                                  (1.0f - w) / (1.0f - 0.088f)), 0.0f);
            return (m >= 0.6f) ? 2 : ((m >= 0.1f) ? 1 : 0);
        };
        ivb[wp * 64 + lane] = (unsigned char)ivf(w0);
        ivb[wp * 64 + 32 + lane] = (unsigned char)ivf(w1);
        __syncwarp();
        if (lane == 0) {
            unsigned long long c0 = 0ull, c1 = 0ull;
            for (int i = 0; i < 32; i++) {
                c0 |= (unsigned long long)ivb[wp * 64 + i] << (2 * i);
                c1 |= (unsigned long long)ivb[wp * 64 + 32 + i] << (2 * i);
            }
            g_code[row * 2] = c0;
            g_code[row * 2 + 1] = c1;
        }
        __syncwarp();
    }
}

// ---------------- src scan + memS / H0 / C0 / read_0 init --------------------
__device__ void stage_init(float* sm, const float* __restrict__ Mv0,
                           const float* __restrict__ hx0, const float* __restrict__ cx0,
                           int r0, int c0)
{
    float* memS = sm;
    float* wT = sm + OFF_WT;
    const int tid = threadIdx.x;
    if (tid < Tlen) {
        const int b = blockIdx.x, i = tid;
        unsigned long long cc0 = g_code[(b * Tlen + i) * 2];
        unsigned long long cc1 = g_code[(b * Tlen + i) * 2 + 1];
        int sv = i - 1;
        for (int j = i - 1; j >= 0; j--)
            if (g_code[(b * Tlen + j) * 2] == cc0 && g_code[(b * Tlen + j) * 2 + 1] == cc1) { sv = j; break; }
        g_src[b * Tlen + i] = sv;
    }
    for (int i = tid; i < 32768; i += NTHR) {
        int m = (i >> 5) & 63, cc = i & 31;
        memS[i] = Mv0[m * Dm + c0 + cc];
    }
    for (int i = tid; i < 1024; i += NTHR) {
        int bl = i >> 6, m = i & 63;
        wT[i] = g_w[((r0 + bl) * Tlen) * 64 + m];
    }
    __syncthreads();
    const int rr = tid >> 5, cc = tid & 31;
    const int b = r0 + rr, col = c0 + cc;
    g_H[(size_t)b * Dm + col] = hx0[col];
    g_C[(size_t)b * Dm + col] = cx0[col];
    float racc = 0.f;
#pragma unroll 4
    for (int m = 0; m < 64; m++)
        racc = fmaf(wT[rr * 64 + m], memS[(rr * 64 + m) * 32 + cc], racc);
    g_read[(size_t)b * Dm + col] = racc;
}

// ---------------- f / we GEMM: tf32 mma, pipelined ----------------------------
template<int MODE>   // 0: f = tanh(.), X=g_read, tab=ktab ; 1: we = raw, X=g_f, tab=xtab
__device__ void stage_fwe(float* sm, const float* __restrict__ bias,
                          const float* __restrict__ tab, const int* __restrict__ q,
                          const int* __restrict__ r, int t, int r0, int c0)
{
    float* As = sm + OFF_AS;
    float* part = sm + OFF_PART;
    int* sQ = (int*)(sm + OFF_I16);
    const int tid = threadIdx.x;
    const int g = tid >> 7, gt = tid & 127;
    const int s = gt >> 5, lane = tid & 31;
    if (tid < 16) {
        int b = r0 + tid;
        int qi = q[b * Tlen + t];
        sQ[tid] = (MODE == 0) ? qi : (qi + 2000 * r[b * Tlen + t]);
    }
    __syncthreads();
    const float* X = (MODE == 0) ? g_read : g_f;
    const float* slab = ((MODE == 0) ? g_WTf : g_WTa2) + ((size_t)(c0 >> 5) << 15);

    const int wk0 = (gt * 2) >> 3, wsg0 = (gt * 2) & 7;
    const int wk1 = (gt * 2 + 1) >> 3, wsg1 = (gt * 2 + 1) & 7;
    float* wb0p = sm + OFF_WS + g * 1184;
    float* wb1p = part + g * 2304;
    unsigned wbu0 = (unsigned)__cvta_generic_to_shared(wb0p);
    unsigned wbu1 = (unsigned)__cvta_generic_to_shared(wb1p);
    const unsigned wo0 = (unsigned)(wk0 * 36 + wsg0 * 4) * 4u;
    const unsigned wo1 = (unsigned)(wk1 * 36 + wsg1 * 4) * 4u;
    const int arr = gt >> 3, akq = gt & 7;

    {
        int kb = g * 256;
        cpa16(wbu0 + wo0, slab + (size_t)(kb + wk0) * 32 + wsg0 * 4);
        cpa16(wbu0 + wo1, slab + (size_t)(kb + wk1) * 32 + wsg1 * 4);
        cpa_commit();
    }
    float4 aR;
    {
        int kb = g * 256;
        const float* srcp = (g < 2) ? X + (size_t)(r0 + arr) * Dm + kb + akq * 4
                                    : tab + (size_t)sQ[arr] * Dm + (kb - Dm) + akq * 4;
        aR = *(const float4*)srcp;
    }
    float dacc[4][4] = {};
    unsigned* Ag = (unsigned*)(As) + g * 640;
#pragma unroll 1
    for (int ch = 0; ch < 8; ch++) {
        if (ch < 7) {
            int kb = g * 256 + (ch + 1) * 32;
            unsigned wd = ((ch + 1) & 1) ? wbu1 : wbu0;
            cpa16(wd + wo0, slab + (size_t)(kb + wk0) * 32 + wsg0 * 4);
            cpa16(wd + wo1, slab + (size_t)(kb + wk1) * 32 + wsg1 * 4);
            cpa_commit();
        }
        {   // store A chunk ch (k-major, tf32)
            unsigned* a = Ag + (akq * 4) * 20 + arr;
            a[0] = f2tf(aR.x); a[20] = f2tf(aR.y); a[40] = f2tf(aR.z); a[60] = f2tf(aR.w);
        }
        float4 aN = aR;
        if (ch < 7) {
            int kb = g * 256 + (ch + 1) * 32;
            const float* srcp = (g < 2) ? X + (size_t)(r0 + arr) * Dm + kb + akq * 4
                                        : tab + (size_t)sQ[arr] * Dm + (kb - Dm) + akq * 4;
            aN = *(const float4*)srcp;
            cpa_wait1();
        } else {
            cpa_wait0();
        }
        barg(g);
        const unsigned* Wb = (const unsigned*)((ch & 1) ? wb1p : wb0p);
        const int kl = s * 8;
        unsigned a0 = Ag[(kl + (lane & 3)) * 20 + (lane >> 2)];
        unsigned a1 = Ag[(kl + (lane & 3)) * 20 + (lane >> 2) + 8];
        unsigned a2 = Ag[(kl + 4 + (lane & 3)) * 20 + (lane >> 2)];
        unsigned a3 = Ag[(kl + 4 + (lane & 3)) * 20 + (lane >> 2) + 8];
#pragma unroll
        for (int nt = 0; nt < 4; nt++) {
            unsigned b0 = Wb[(kl + (lane & 3)) * 36 + nt * 8 + (lane >> 2)];
            unsigned b1 = Wb[(kl + 4 + (lane & 3)) * 36 + nt * 8 + (lane >> 2)];
            mma_tf32(dacc[nt], a0, a1, a2, a3, b0, b1);
        }
        aR = aN;
        barg(g);
    }
    const int sid = g * 4 + s;
    {
        const int row = lane >> 2, colb = (lane & 3) * 2;
        float* pb = part + sid * 576;
#pragma unroll
        for (int nt = 0; nt < 4; nt++) {
            pb[row * 36 + nt * 8 + colb]           = dacc[nt][0];
            pb[row * 36 + nt * 8 + colb + 1]       = dacc[nt][1];
            pb[(row + 8) * 36 + nt * 8 + colb]     = dacc[nt][2];
            pb[(row + 8) * 36 + nt * 8 + colb + 1] = dacc[nt][3];
        }
    }
    __syncthreads();
    {
        const int rr = tid >> 5, cc = tid & 31;
        float v = 0.f;
#pragma unroll
        for (int p = 0; p < 16; p++) v += part[p * 576 + rr * 36 + cc];
        v += bias[c0 + cc];
        const int b = r0 + rr;
        if (MODE == 0) {
            v = tanhf(v);
            g_f[(size_t)b * Dm + c0 + cc] = v;
            g_ft[((size_t)t * Bsz + b) * Dm + c0 + cc] = v;
        } else {
            g_we[(size_t)b * Dm + c0 + cc] = v;
        }
    }
}

// ---------------- e/a GEMMs (tf32 mma) + smem memory update ------------------
__device__ void stage_ea(float* sm, const float* __restrict__ be,
                         const float* __restrict__ ba, int t, int r0, int c0)
{
    float* memS = sm;
    float* As = sm + OFF_AS;
    float* part = sm + OFF_PART;
    float* wT = sm + OFF_WT;
    float* wN = sm + OFF_WN;
    const int tid = threadIdx.x;
    const int g = tid >> 7, gt = tid & 127;
    const int s = gt >> 5, lane = tid & 31;
    for (int i = tid; i < 1024; i += NTHR) {
        int bl = i >> 6, m = i & 63;
        wT[i] = g_w[((r0 + bl) * Tlen + t) * 64 + m];
        wN[i] = (t + 1 < Tlen) ? g_w[((r0 + bl) * Tlen + t + 1) * 64 + m] : 0.0f;
    }
    __syncthreads();
    const float* slab = ((g < 2) ? g_WTe : g_WTad) + ((size_t)(c0 >> 5) << 14);

    const int wk0 = (gt * 2) >> 3, wsg0 = (gt * 2) & 7;
    const int wk1 = (gt * 2 + 1) >> 3, wsg1 = (gt * 2 + 1) & 7;
    float* wb0p = sm + OFF_WS + g * 1184;
    float* wb1p = part + g * 2304;
    unsigned wbu0 = (unsigned)__cvta_generic_to_shared(wb0p);
    unsigned wbu1 = (unsigned)__cvta_generic_to_shared(wb1p);
    const unsigned wo0 = (unsigned)(wk0 * 36 + wsg0 * 4) * 4u;
    const unsigned wo1 = (unsigned)(wk1 * 36 + wsg1 * 4) * 4u;
    const int arr = gt >> 3, akq = gt & 7;
    const int kh = (g & 1) * 256;

    {
        cpa16(wbu0 + wo0, slab + (size_t)(kh + wk0) * 32 + wsg0 * 4);
        cpa16(wbu0 + wo1, slab + (size_t)(kh + wk1) * 32 + wsg1 * 4);
        cpa_commit();
    }
    float4 aR = *(const float4*)(g_we + (size_t)(r0 + arr) * Dm + kh + akq * 4);
    float dacc[4][4] = {};
    unsigned* Ag = (unsigned*)(As) + g * 640;
#pragma unroll 1
    for (int ch = 0; ch < 8; ch++) {
        if (ch < 7) {
            int kb = kh + (ch + 1) * 32;
            unsigned wd = ((ch + 1) & 1) ? wbu1 : wbu0;
            cpa16(wd + wo0, slab + (size_t)(kb + wk0) * 32 + wsg0 * 4);
            cpa16(wd + wo1, slab + (size_t)(kb + wk1) * 32 + wsg1 * 4);
            cpa_commit();
        }
        {
            unsigned* a = Ag + (akq * 4) * 20 + arr;
            a[0] = f2tf(aR.x); a[20] = f2tf(aR.y); a[40] = f2tf(aR.z); a[60] = f2tf(aR.w);
        }
        float4 aN = aR;
        if (ch < 7) {
            int kb = kh + (ch + 1) * 32;
            aN = *(const float4*)(g_we + (size_t)(r0 + arr) * Dm + kb + akq * 4);
            cpa_wait1();
        } else {
            cpa_wait0();
        }
        barg(g);
        const unsigned* Wb = (const unsigned*)((ch & 1) ? wb1p : wb0p);
        const int kl = s * 8;
        unsigned a0 = Ag[(kl + (lane & 3)) * 20 + (lane >> 2)];
        unsigned a1 = Ag[(kl + (lane & 3)) * 20 + (lane >> 2) + 8];
        unsigned a2 = Ag[(kl + 4 + (lane & 3)) * 20 + (lane >> 2)];
        unsigned a3 = Ag[(kl + 4 + (lane & 3)) * 20 + (lane >> 2) + 8];
#pragma unroll
        for (int nt = 0; nt < 4; nt++) {
            unsigned b0 = Wb[(kl + (lane & 3)) * 36 + nt * 8 + (lane >> 2)];
            unsigned b1 = Wb[(kl + 4 + (lane & 3)) * 36 + nt * 8 + (lane >> 2)];
            mma_tf32(dacc[nt], a0, a1, a2, a3, b0, b1);
        }
        aR = aN;
        barg(g);
    }
    const int sid = g * 4 + s;
    {
        const int row = lane >> 2, colb = (lane & 3) * 2;
        float* pb = part + sid * 576;
#pragma unroll
        for (int nt = 0; nt < 4; nt++) {
            pb[row * 36 + nt * 8 + colb]           = dacc[nt][0];
            pb[row * 36 + nt * 8 + colb + 1]       = dacc[nt][1];
            pb[(row + 8) * 36 + nt * 8 + colb]     = dacc[nt][2];
            pb[(row + 8) * 36 + nt * 8 + colb + 1] = dacc[nt][3];
        }
    }
    __syncthreads();
    {
        const int rr = tid >> 5, cc = tid & 31;
        float ve = 0.f, va = 0.f;
#pragma unroll
        for (int p = 0; p < 8; p++)  ve += part[p * 576 + rr * 36 + cc];
#pragma unroll
        for (int p = 8; p < 16; p++) va += part[p * 576 + rr * 36 + cc];
        ve = sigm(ve + be[c0 + cc]);
        va = tanhf(va + ba[c0 + cc]);
        float racc = 0.f;
#pragma unroll 4
        for (int m = 0; m < 64; m++) {
            float wt = wT[rr * 64 + m], wn = wN[rr * 64 + m];
            float* p = &memS[(rr * 64 + m) * 32 + cc];
            float v = *p;
            v = v * (1.0f - wt * ve) + wt * va;
            *p = v;
            racc = fmaf(wn, v, racc);
        }
        g_read[(size_t)(r0 + rr) * Dm + c0 + cc] = racc;
    }
}

// ---------------- hop-LSTM step: tf32 mma.sync, 16 x 64-k chunks --------------
__device__ void stage_lstm(float* sm, const float* __restrict__ bih,
                           const float* __restrict__ bhh, int t, int r0, int c0)
{
    float* part = sm + OFF_PART;
    int* s16 = (int*)(sm + OFF_I16);
    const int tid = threadIdx.x;
    const int w = tid >> 5, lane = tid & 31;
    const int gate = w >> 2, ks = w & 3;
    const int g = tid >> 7, gt = tid & 127;
    if (tid < 16) s16[tid] = g_src[(r0 + tid) * Tlen + t] + 1;
    __syncthreads();

    const float* slab = g_WTl + ((size_t)((c0 >> 5) * 4 + g) << 15);
    int wk[4], wsg[4]; unsigned wo[4];
#pragma unroll
    for (int h = 0; h < 4; h++) {
        int i = gt * 4 + h;
        wk[h] = i >> 3; wsg[h] = i & 7;
        wo[h] = (unsigned)(wk[h] * 36 + wsg[h] * 4) * 4u;
    }
    float* wbB0 = sm + g * 2304;
    float* wbB1 = sm + 9216 + g * 2304;
    unsigned wbu0 = (unsigned)__cvta_generic_to_shared(wbB0);
    unsigned wbu1 = (unsigned)__cvta_generic_to_shared(wbB1);
    float* aLp = sm + 18432;
    unsigned* aLu = (unsigned*)aLp;

    const int arow = tid & 15, aseg = tid >> 4;
    const float* aF = g_ft + ((size_t)t * Bsz + r0 + arow) * Dm + aseg * 4;
    const float* aH = g_H + ((size_t)s16[arow] * Bsz + r0 + arow) * Dm + aseg * 4;

    {
#pragma unroll
        for (int h = 0; h < 4; h++)
            cpa16(wbu0 + wo[h], slab + (size_t)wk[h] * 32 + wsg[h] * 4);
        cpa_commit();
    }
    float4 aR = make_float4(0.f, 0.f, 0.f, 0.f);
    if (tid < 256) aR = *(const float4*)aF;

    float dacc[4][4] = {};
#pragma unroll 1
    for (int ch = 0; ch < 16; ch++) {
        if (ch < 15) {
            int kb = (ch + 1) * 64;
            unsigned wd = ((ch + 1) & 1) ? wbu1 : wbu0;
#pragma unroll
            for (int h = 0; h < 4; h++)
                cpa16(wd + wo[h], slab + (size_t)(kb + wk[h]) * 32 + wsg[h] * 4);
            cpa_commit();
        }
        if (tid < 256) {
            unsigned* a = aLu + (aseg * 4) * 20 + arow;
            a[0]  = f2tf(aR.x); a[20] = f2tf(aR.y);
            a[40] = f2tf(aR.z); a[60] = f2tf(aR.w);
        }
        float4 aN = aR;
        if (ch < 15) {
            int kb = (ch + 1) * 64;
            if (tid < 256) {
                const float* basep = (kb < Dm) ? aF + kb : aH + (kb - Dm);
                aN = *(const float4*)basep;
            }
            cpa_wait1();
        } else {
            cpa_wait0();
        }
        __syncthreads();
        const unsigned* Wg = (const unsigned*)(((ch & 1) ? (sm + 9216) : sm)) + gate * 2304;
#pragma unroll
        for (int kt = 0; kt < 2; kt++) {
            const int kl = ks * 16 + kt * 8;
            unsigned a0 = aLu[(kl + (lane & 3)) * 20 + (lane >> 2)];
            unsigned a1 = aLu[(kl + (lane & 3)) * 20 + (lane >> 2) + 8];
            unsigned a2 = aLu[(kl + 4 + (lane & 3)) * 20 + (lane >> 2)];
            unsigned a3 = aLu[(kl + 4 + (lane & 3)) * 20 + (lane >> 2) + 8];
#pragma unroll
            for (int nt = 0; nt < 4; nt++) {
                unsigned b0 = Wg[(kl + (lane & 3)) * 36 + nt * 8 + (lane >> 2)];
                unsigned b1 = Wg[(kl + 4 + (lane & 3)) * 36 + nt * 8 + (lane >> 2)];
                mma_tf32(dacc[nt], a0, a1, a2, a3, b0, b1);
            }
        }
        aR = aN;
        __syncthreads();
    }
    const int sid = gate * 4 + ks;
    {
        const int row = lane >> 2, colb = (lane & 3) * 2;
#pragma unroll
        for (int nt = 0; nt < 4; nt++) {
            float* pb = part + sid * 576;
            pb[row * 36 + nt * 8 + colb]           = dacc[nt][0];
            pb[row * 36 + nt * 8 + colb + 1]       = dacc[nt][1];
            pb[(row + 8) * 36 + nt * 8 + colb]     = dacc[nt][2];
            pb[(row + 8) * 36 + nt * 8 + colb + 1] = dacc[nt][3];
        }
    }
    __syncthreads();
    {
        const int rr = tid >> 5, cc = tid & 31;
        float gi = 0.f, gf = 0.f, gg = 0.f, go = 0.f;
#pragma unroll
        for (int p = 0; p < 4; p++)   gi += part[p * 576 + rr * 36 + cc];
#pragma unroll
        for (int p = 4; p < 8; p++)   gf += part[p * 576 + rr * 36 + cc];
#pragma unroll
        for (int p = 8; p < 12; p++)  gg += part[p * 576 + rr * 36 + cc];
#pragma unroll
        for (int p = 12; p < 16; p++) go += part[p * 576 + rr * 36 + cc];
        const int b = r0 + rr, col = c0 + cc;
        gi += bih[col] + bhh[col];
        gf += bih[512 + col] + bhh[512 + col];
        gg += bih[1024 + col] + bhh[1024 + col];
        go += bih[1536 + col] + bhh[1536 + col];
        float cin = g_C[((size_t)s16[rr] * Bsz + b) * Dm + col];
        float cn = sigm(gf) * cin + sigm(gi) * tanhf(gg);
        float hn = sigm(go) * tanhf(cn);
        g_C[((size_t)(t + 1) * Bsz + b) * Dm + col] = cn;
        g_H[((size_t)(t + 1) * Bsz + b) * Dm + col] = hn;
    }
}

// ---------------- prediction head --------------------------------------------
__device__ void stage_head(const float* __restrict__ Wp, const float* __restrict__ bp,
                           float* __restrict__ out)
{
    const int wp = threadIdx.x >> 5, lane = threadIdx.x & 31;
    for (int bt = blockIdx.x * 16 + wp; bt < Bsz * Tlen; bt += NBLK * 16) {
        const int b = bt / Tlen, t = bt % Tlen;
        const float* h = &g_H[((size_t)(t + 1) * Bsz + b) * Dm];
        float s = 0.f;
        for (int i = lane; i < Dm; i += 32) s = fmaf(h[i], Wp[i], s);
        for (int o = 16; o; o >>= 1) s += __shfl_xor_sync(0xffffffffu, s, o);
        if (lane == 0) out[bt] = sigm(s + bp[0]);
    }
}

// ---------------- the single persistent kernel -------------------------------
__global__ void __launch_bounds__(NTHR, 1) k_persist(
    const int* __restrict__ q, const int* __restrict__ r,
    const float* __restrict__ Mk, const float* __restrict__ Mv0,
    const float* __restrict__ ktab, const float* __restrict__ xtab,
    const float* __restrict__ We, const float* __restrict__ be,
    const float* __restrict__ Wadd, const float* __restrict__ badd,
    const float* __restrict__ Wa, const float* __restrict__ ba,
    const float* __restrict__ Wf, const float* __restrict__ bf,
    const float* __restrict__ Wih, const float* __restrict__ Whh,
    const float* __restrict__ bih, const float* __restrict__ bhh,
    const float* __restrict__ hx0, const float* __restrict__ cx0,
    const float* __restrict__ Wp, const float* __restrict__ bp,
    float* __restrict__ out)
{
    extern __shared__ float sm[];
    const int grp = blockIdx.x & 7;
    const int grp32 = grp * 32;
    unsigned ls = 0, lsr = 0;
    if (threadIdx.x == 0) { ls = g_sense; lsr = g_gsense[grp32]; }
    const int r0 = grp * 16;
    const int c0 = (blockIdx.x >> 3) * 32;

    stage_wtr(Wf, Wa, We, Wadd, Wih, Whh);
    stage_addr(sm, Mk, ktab, q);                          gsync(ls);
    stage_softmax(sm);                                    gsync(ls);
    stage_init(sm, Mv0, hx0, cx0, r0, c0);                gsync(ls);

    for (int t = 0; t < Tlen; t++) {
        stage_fwe<0>(sm, bf, ktab, q, r, t, r0, c0);      gsync_grp(lsr, grp32);
        stage_fwe<1>(sm, ba, xtab, q, r, t, r0, c0);      gsync_grp(lsr, grp32);
        stage_ea(sm, be, badd, t, r0, c0);                gsync_grp(lsr, grp32);
    }
    for (int t = 0; t < Tlen; t++) {
        stage_lstm(sm, bih, bhh, t, r0, c0);              gsync_grp(lsr, grp32);
    }
    gsync(ls);                                            // head reads all rows
    stage_head(Wp, bp, out);
}

// ----------------------------------------------------------------------------
extern "C" void kernel_launch(void* const* d_in, const int* in_sizes, int n_in,
                              void* d_out, int out_size)
{
    const int*   q    = (const int*)d_in[0];
    const int*   r    = (const int*)d_in[1];
    const float* Mk   = (const float*)d_in[2];
    const float* Mv0  = (const float*)d_in[3];
    const float* ktab = (const float*)d_in[4];
    const float* xtab = (const float*)d_in[5];
    const float* We   = (const float*)d_in[6];
    const float* be   = (const float*)d_in[7];
    const float* Wadd = (const float*)d_in[8];
    const float* badd = (const float*)d_in[9];
    const float* Wa   = (const float*)d_in[10];
    const float* ba   = (const float*)d_in[11];
    const float* Wf   = (const float*)d_in[12];
    const float* bf   = (const float*)d_in[13];
    const float* Wih  = (const float*)d_in[14];
    const float* Whh  = (const float*)d_in[15];
    const float* bih  = (const float*)d_in[16];
    const float* bhh  = (const float*)d_in[17];
    const float* hx0  = (const float*)d_in[18];
    const float* cx0  = (const float*)d_in[19];
    const float* Wp   = (const float*)d_in[20];
    const float* bp   = (const float*)d_in[21];
    float* out = (float*)d_out;

    static bool attr_set = false;
    if (!attr_set) {
        cudaFuncSetAttribute(k_persist, cudaFuncAttributeMaxDynamicSharedMemorySize, SMEM_BYTES);
        attr_set = true;
    }
    k_persist<<<NBLK, NTHR, SMEM_BYTES>>>(q, r, Mk, Mv0, ktab, xtab, We, be, Wadd, badd,
                                          Wa, ba, Wf, bf, Wih, Whh, bih, bhh,
                                          hx0, cx0, Wp, bp, out);
}